// round 7
// baseline (speedup 1.0000x reference)
#include <cuda_runtime.h>
#include <cuda_bf16.h>
#include <cstdint>
#include <math.h>

// Problem dims
#define BB 2
#define TT 2048
#define CC 1024
#define HH 16
#define DD 64
#define C3 3072
#define MM (BB * TT)   // 4096

// ---------------------------------------------------------------------------
// Scratch (device globals; no allocation allowed)
// ---------------------------------------------------------------------------
__device__ __nv_bfloat16 g_xh[(size_t)MM * CC];
__device__ __nv_bfloat16 g_xl[(size_t)MM * CC];
__device__ __nv_bfloat16 g_wah[(size_t)C3 * CC];
__device__ __nv_bfloat16 g_wal[(size_t)C3 * CC];
__device__ __nv_bfloat16 g_wph[(size_t)CC * CC];
__device__ __nv_bfloat16 g_wpl[(size_t)CC * CC];
__device__ __nv_bfloat16 g_qkvh[(size_t)MM * C3];
__device__ __nv_bfloat16 g_qkvl[(size_t)MM * C3];
__device__ __nv_bfloat16 g_yh[(size_t)MM * CC];
__device__ __nv_bfloat16 g_yl[(size_t)MM * CC];

// ---------------------------------------------------------------------------
// Helpers (sm_103 base-target: ldmatrix / mma.sync / cp.async)
// ---------------------------------------------------------------------------
__device__ __forceinline__ uint32_t smem_to_u32(const void* p) {
    uint32_t a;
    asm("{ .reg .u64 t; cvta.to.shared.u64 t, %1; cvt.u32.u64 %0, t; }"
        : "=r"(a) : "l"(p));
    return a;
}

#define SWZ(off) ((off) ^ (((off) >> 3) & 0x70))

__device__ __forceinline__ void cp16(uint32_t saddr, const void* g) {
    asm volatile("cp.async.cg.shared.global [%0], [%1], 16;"
                 :: "r"(saddr), "l"(g));
}
#define CP_COMMIT() asm volatile("cp.async.commit_group;" ::: "memory")
#define CP_WAIT(n)  asm volatile("cp.async.wait_group %0;" :: "n"(n) : "memory")

#define LDSM4(r, addr) \
    asm volatile("ldmatrix.sync.aligned.m8n8.x4.shared.b16 {%0,%1,%2,%3}, [%4];" \
        : "=r"((r)[0]), "=r"((r)[1]), "=r"((r)[2]), "=r"((r)[3]) : "r"(addr))

#define LDSM4T(r, addr) \
    asm volatile("ldmatrix.sync.aligned.m8n8.x4.trans.shared.b16 {%0,%1,%2,%3}, [%4];" \
        : "=r"((r)[0]), "=r"((r)[1]), "=r"((r)[2]), "=r"((r)[3]) : "r"(addr))

#define MMA16816(d, a, b0v, b1v) \
    asm volatile("mma.sync.aligned.m16n8k16.row.col.f32.bf16.bf16.f32 " \
        "{%0,%1,%2,%3}, {%4,%5,%6,%7}, {%8,%9}, {%0,%1,%2,%3};" \
        : "+f"((d)[0]), "+f"((d)[1]), "+f"((d)[2]), "+f"((d)[3]) \
        : "r"((a)[0]), "r"((a)[1]), "r"((a)[2]), "r"((a)[3]), "r"(b0v), "r"(b1v))

__device__ __forceinline__ uint32_t pack_bf16x2(float a, float b) {
    __nv_bfloat162 t = __floats2bfloat162_rn(a, b);
    return *(uint32_t*)&t;
}

// ---------------------------------------------------------------------------
// Split fp32 -> bf16 hi/lo planes
// ---------------------------------------------------------------------------
__global__ void __launch_bounds__(256) split_f32(const float* __restrict__ in,
                                                 __nv_bfloat16* __restrict__ hi,
                                                 __nv_bfloat16* __restrict__ lo,
                                                 int n4) {
    int i = blockIdx.x * 256 + threadIdx.x;
    if (i >= n4) return;
    float4 v = ((const float4*)in)[i];
    __nv_bfloat16 h0 = __float2bfloat16(v.x);
    __nv_bfloat16 h1 = __float2bfloat16(v.y);
    __nv_bfloat16 h2 = __float2bfloat16(v.z);
    __nv_bfloat16 h3 = __float2bfloat16(v.w);
    __nv_bfloat16 l0 = __float2bfloat16(v.x - __bfloat162float(h0));
    __nv_bfloat16 l1 = __float2bfloat16(v.y - __bfloat162float(h1));
    __nv_bfloat16 l2 = __float2bfloat16(v.z - __bfloat162float(h2));
    __nv_bfloat16 l3 = __float2bfloat16(v.w - __bfloat162float(h3));
    ((__nv_bfloat162*)hi)[i * 2 + 0] = __nv_bfloat162(h0, h1);
    ((__nv_bfloat162*)hi)[i * 2 + 1] = __nv_bfloat162(h2, h3);
    ((__nv_bfloat162*)lo)[i * 2 + 0] = __nv_bfloat162(l0, l1);
    ((__nv_bfloat162*)lo)[i * 2 + 1] = __nv_bfloat162(l2, l3);
}

// ---------------------------------------------------------------------------
// HMMA GEMM: C[M,N] = A[M,K] @ B[N,K]^T, fp32-accurate via bf16 3-term split.
// Tile 128x128, K-chunk 32, 512 threads (16 warps = 4m x 4n), warp tile 32x32.
// 3-stage cp.async pipeline @ 96KB smem -> 2 CTAs/SM; 1 barrier per chunk.
// SPLIT=true: write bf16 hi/lo planes (scaling cols<1024 by 0.125 for Q).
// ---------------------------------------------------------------------------
#define NSTAGE 3
#define STAGE_BYTES 32768
#define GEMM_SMEM (NSTAGE * STAGE_BYTES)   // 98304

template <bool SPLIT>
__global__ void __launch_bounds__(512, 2) gemm_hmma3(
    const __nv_bfloat16* __restrict__ Ah, const __nv_bfloat16* __restrict__ Al,
    const __nv_bfloat16* __restrict__ Bh, const __nv_bfloat16* __restrict__ Bl,
    float* __restrict__ C, __nv_bfloat16* __restrict__ Ch,
    __nv_bfloat16* __restrict__ Cl, int M, int N, int K) {
    extern __shared__ char smem[];
    const uint32_t sbase = smem_to_u32(smem);
    const int tid = threadIdx.x;
    const int lane = tid & 31;
    const int wid = tid >> 5;      // 0..15
    const int wm = wid >> 2;       // 0..3
    const int wn = wid & 3;        // 0..3
    const int bm = blockIdx.y * 128;
    const int bn = blockIdx.x * 128;

    float acc[2][4][4];
#pragma unroll
    for (int i = 0; i < 2; i++)
#pragma unroll
        for (int j = 0; j < 4; j++)
#pragma unroll
            for (int t = 0; t < 4; t++) acc[i][j][t] = 0.f;

    const int nch = K >> 5;
    const int rowL = tid >> 3;     // 0..63
    const int uL = tid & 7;        // 16B unit: 0-3 hi plane, 4-7 lo plane

    auto ld_chunk = [&](int c, int st) {
        const int k0 = c << 5;
        const uint32_t sA = sbase + st * STAGE_BYTES;
        const uint32_t sB = sA + 16384;
        const int kk = k0 + (uL & 3) * 8;
        const bool isHi = (uL < 4);
        const __nv_bfloat16* gA = (isHi ? Ah : Al);
        const __nv_bfloat16* gB = (isHi ? Bh : Bl);
#pragma unroll
        for (int it = 0; it < 2; it++) {
            int row = rowL + it * 64;
            cp16(sA + SWZ(row * 128 + uL * 16), gA + (size_t)(bm + row) * K + kk);
            cp16(sB + SWZ(row * 128 + uL * 16), gB + (size_t)(bn + row) * K + kk);
        }
    };

    auto compute = [&](int st) {
        const uint32_t sA = sbase + st * STAGE_BYTES;
        const uint32_t sB = sA + 16384;
#pragma unroll
        for (int ks = 0; ks < 2; ks++) {
            uint32_t ah[2][4], al[2][4];
            const int rA = lane & 15;
            const int uA = ks * 2 + (lane >> 4);
#pragma unroll
            for (int mi = 0; mi < 2; mi++) {
                int mrow = wm * 32 + mi * 16 + rA;
                LDSM4(ah[mi], sA + SWZ(mrow * 128 + uA * 16));
                LDSM4(al[mi], sA + SWZ(mrow * 128 + (uA + 4) * 16));
            }
            const int rB = (lane & 7) + ((lane & 16) >> 1);
            const int uB = ks * 2 + ((lane & 8) >> 3);
#pragma unroll
            for (int nb = 0; nb < 2; nb++) {
                int nrow = wn * 32 + nb * 16 + rB;
                uint32_t bh[4], bl[4];
                LDSM4(bh, sB + SWZ(nrow * 128 + uB * 16));
                LDSM4(bl, sB + SWZ(nrow * 128 + (uB + 4) * 16));
#pragma unroll
                for (int mi = 0; mi < 2; mi++) {
                    MMA16816(acc[mi][nb * 2 + 0], ah[mi], bh[0], bh[1]);
                    MMA16816(acc[mi][nb * 2 + 1], ah[mi], bh[2], bh[3]);
                    MMA16816(acc[mi][nb * 2 + 0], ah[mi], bl[0], bl[1]);
                    MMA16816(acc[mi][nb * 2 + 1], ah[mi], bl[2], bl[3]);
                    MMA16816(acc[mi][nb * 2 + 0], al[mi], bh[0], bh[1]);
                    MMA16816(acc[mi][nb * 2 + 1], al[mi], bh[2], bh[3]);
                }
            }
        }
    };

    // 2-deep prologue into 3 stages
    ld_chunk(0, 0); CP_COMMIT();
    ld_chunk(1, 1); CP_COMMIT();

    for (int c = 0; c < nch; c++) {
        if (c + 1 < nch) CP_WAIT(1);
        else             CP_WAIT(0);
        __syncthreads();
        // Issue next load first (stage (c+2)%3 == (c-1)%3, whose readers all
        // finished compute(c-1) before the barrier above).
        if (c + 2 < nch) {
            int st = c + 2;
            ld_chunk(st, st - (st / NSTAGE) * NSTAGE);
            CP_COMMIT();
        }
        compute(c - (c / NSTAGE) * NSTAGE);
    }

    // Epilogue
    const int er = lane >> 2;
    const int ec = (lane & 3) * 2;
    const float sc = (SPLIT && bn < 1024) ? 0.125f : 1.0f;  // fold q scale
#pragma unroll
    for (int mi = 0; mi < 2; mi++) {
#pragma unroll
        for (int nj = 0; nj < 4; nj++) {
            int row = bm + wm * 32 + mi * 16 + er;
            int col = bn + wn * 32 + nj * 8 + ec;
            if (SPLIT) {
#pragma unroll
                for (int rr = 0; rr < 2; rr++) {
                    float a0 = acc[mi][nj][rr * 2 + 0] * sc;
                    float a1 = acc[mi][nj][rr * 2 + 1] * sc;
                    __nv_bfloat16 h0 = __float2bfloat16(a0);
                    __nv_bfloat16 h1 = __float2bfloat16(a1);
                    __nv_bfloat16 l0 = __float2bfloat16(a0 - __bfloat162float(h0));
                    __nv_bfloat16 l1 = __float2bfloat16(a1 - __bfloat162float(h1));
                    size_t off = (size_t)(row + rr * 8) * N + col;
                    *(__nv_bfloat162*)(Ch + off) = __nv_bfloat162(h0, h1);
                    *(__nv_bfloat162*)(Cl + off) = __nv_bfloat162(l0, l1);
                }
            } else {
                float2 v0 = make_float2(acc[mi][nj][0], acc[mi][nj][1]);
                float2 v1 = make_float2(acc[mi][nj][2], acc[mi][nj][3]);
                *(float2*)(C + (size_t)row * N + col) = v0;
                *(float2*)(C + (size_t)(row + 8) * N + col) = v1;
            }
        }
    }
}

// ---------------------------------------------------------------------------
// HMMA flash attention (causal). CTA = 128 q rows, 8 warps (16 rows each).
// Unchanged from round 6 (passes).
// ---------------------------------------------------------------------------
#define AQH 0
#define AQL 16384
#define AST(s) (32768 + (s) * 32768)   // stage: KH +0, KL +8192, VH +16384, VL +24576
#define ATTN_SMEM (32768 + 2 * 32768)  // 98304

__global__ void __launch_bounds__(256) attn_hmma(
    const __nv_bfloat16* __restrict__ qkvh, const __nv_bfloat16* __restrict__ qkvl,
    __nv_bfloat16* __restrict__ yh, __nv_bfloat16* __restrict__ yl) {
    extern __shared__ char smem[];
    const uint32_t sb = smem_to_u32(smem);
    const int qt = blockIdx.x;
    const int h  = blockIdx.y;
    const int b  = blockIdx.z;
    const int tid = threadIdx.x;
    const int lane = tid & 31;
    const int wid = tid >> 5;

    const size_t tok0 = (size_t)b * TT;

    // ---- Q tile load (128 rows x 64 d, hi+lo) ----
    {
        const int u = tid & 7;
        const int r = tid >> 3;
#pragma unroll
        for (int p = 0; p < 2; p++) {
            const __nv_bfloat16* gq =
                (p ? qkvl : qkvh) + (tok0 + (size_t)qt * 128) * C3 + h * DD + u * 8;
            const uint32_t sq = sb + (p ? AQL : AQH);
#pragma unroll
            for (int it = 0; it < 4; it++) {
                int row = r + it * 32;
                cp16(sq + SWZ(row * 128 + u * 16), gq + (size_t)row * C3);
            }
        }
    }

    auto ld_kv = [&](int kc, int st) {
        const int u = tid & 7;
        const int r = tid >> 3;
        const uint32_t sst = sb + AST(st);
        const size_t trow = tok0 + (size_t)kc * 64;
#pragma unroll
        for (int p = 0; p < 4; p++) {   // KH, KL, VH, VL
            const __nv_bfloat16* g = ((p & 1) ? qkvl : qkvh) + trow * C3 +
                                     ((p < 2) ? CC : 2 * CC) + h * DD + u * 8;
            const uint32_t sdst = sst + p * 8192;
#pragma unroll
            for (int it = 0; it < 2; it++) {
                int row = r + it * 32;
                cp16(sdst + SWZ(row * 128 + u * 16), g + (size_t)row * C3);
            }
        }
    };

    const int nch = 2 * qt + 2;
    ld_kv(0, 0);
    CP_COMMIT();
    if (nch > 1) { ld_kv(1, 1); CP_COMMIT(); }

    uint32_t qh[4][4], ql[4][4];
    float o[8][4];
#pragma unroll
    for (int j = 0; j < 8; j++)
#pragma unroll
        for (int t = 0; t < 4; t++) o[j][t] = 0.f;
    float m0 = -1e30f, m1 = -1e30f, l0 = 0.f, l1 = 0.f;

    const int qrow_lo = qt * 128 + wid * 16;
    const int r0 = lane >> 2;
    const int c0 = (lane & 3) * 2;

    for (int kc = 0; kc < nch; kc++) {
        if (kc + 1 < nch) CP_WAIT(1); else CP_WAIT(0);
        __syncthreads();

        if (kc == 0) {
#pragma unroll
            for (int ks = 0; ks < 4; ks++) {
                const int rA = lane & 15;
                const int uA = ks * 2 + (lane >> 4);
                uint32_t a = SWZ((wid * 16 + rA) * 128 + uA * 16);
                LDSM4(qh[ks], sb + AQH + a);
                LDSM4(ql[ks], sb + AQL + a);
            }
        }

        if (kc * 64 <= qrow_lo + 15) {
            const uint32_t sK  = sb + AST(kc & 1);
            const uint32_t sKl = sK + 8192;
            const uint32_t sV  = sK + 16384;
            const uint32_t sVl = sK + 24576;

            float s[8][4];
#pragma unroll
            for (int j = 0; j < 8; j++)
#pragma unroll
                for (int t = 0; t < 4; t++) s[j][t] = 0.f;

            const int rB = (lane & 7) + ((lane & 16) >> 1);
#pragma unroll
            for (int ks = 0; ks < 4; ks++) {
                const int uB = ks * 2 + ((lane & 8) >> 3);
#pragma unroll
                for (int nb = 0; nb < 4; nb++) {
                    uint32_t kh4[4], kl4[4];
                    uint32_t a = SWZ((nb * 16 + rB) * 128 + uB * 16);
                    LDSM4(kh4, sK + a);
                    LDSM4(kl4, sKl + a);
                    MMA16816(s[nb * 2 + 0], qh[ks], kh4[0], kh4[1]);
                    MMA16816(s[nb * 2 + 1], qh[ks], kh4[2], kh4[3]);
                    MMA16816(s[nb * 2 + 0], qh[ks], kl4[0], kl4[1]);
                    MMA16816(s[nb * 2 + 1], qh[ks], kl4[2], kl4[3]);
                    MMA16816(s[nb * 2 + 0], ql[ks], kh4[0], kh4[1]);
                    MMA16816(s[nb * 2 + 1], ql[ks], kh4[2], kh4[3]);
                }
            }

            if (kc * 64 + 63 > qrow_lo) {
                const int qr0 = qrow_lo + r0;
#pragma unroll
                for (int j = 0; j < 8; j++) {
                    int kcol = kc * 64 + 8 * j + c0;
                    if (kcol > qr0)     s[j][0] = -1e30f;
                    if (kcol + 1 > qr0) s[j][1] = -1e30f;
                    if (kcol > qr0 + 8)     s[j][2] = -1e30f;
                    if (kcol + 1 > qr0 + 8) s[j][3] = -1e30f;
                }
            }

            float mx0 = -1e30f, mx1 = -1e30f;
#pragma unroll
            for (int j = 0; j < 8; j++) {
                mx0 = fmaxf(mx0, fmaxf(s[j][0], s[j][1]));
                mx1 = fmaxf(mx1, fmaxf(s[j][2], s[j][3]));
            }
            mx0 = fmaxf(mx0, __shfl_xor_sync(0xffffffffu, mx0, 1));
            mx0 = fmaxf(mx0, __shfl_xor_sync(0xffffffffu, mx0, 2));
            mx1 = fmaxf(mx1, __shfl_xor_sync(0xffffffffu, mx1, 1));
            mx1 = fmaxf(mx1, __shfl_xor_sync(0xffffffffu, mx1, 2));
            float mn0 = fmaxf(m0, mx0);
            float mn1 = fmaxf(m1, mx1);
            float corr0 = __expf(m0 - mn0);
            float corr1 = __expf(m1 - mn1);
            float ls0 = 0.f, ls1 = 0.f;
#pragma unroll
            for (int j = 0; j < 8; j++) {
                s[j][0] = __expf(s[j][0] - mn0);
                s[j][1] = __expf(s[j][1] - mn0);
                s[j][2] = __expf(s[j][2] - mn1);
                s[j][3] = __expf(s[j][3] - mn1);
                ls0 += s[j][0] + s[j][1];
                ls1 += s[j][2] + s[j][3];
            }
            ls0 += __shfl_xor_sync(0xffffffffu, ls0, 1);
            ls0 += __shfl_xor_sync(0xffffffffu, ls0, 2);
            ls1 += __shfl_xor_sync(0xffffffffu, ls1, 1);
            ls1 += __shfl_xor_sync(0xffffffffu, ls1, 2);
            l0 = l0 * corr0 + ls0;
            l1 = l1 * corr1 + ls1;
            m0 = mn0; m1 = mn1;
#pragma unroll
            for (int j = 0; j < 8; j++) {
                o[j][0] *= corr0; o[j][1] *= corr0;
                o[j][2] *= corr1; o[j][3] *= corr1;
            }

            uint32_t ph[4][4], pl[4][4];
#pragma unroll
            for (int ks = 0; ks < 4; ks++) {
                const int j0 = 2 * ks, j1 = 2 * ks + 1;
                float v0 = s[j0][0], v1 = s[j0][1], v2 = s[j0][2], v3 = s[j0][3];
                float w0 = s[j1][0], w1 = s[j1][1], w2 = s[j1][2], w3 = s[j1][3];
                ph[ks][0] = pack_bf16x2(v0, v1);
                ph[ks][1] = pack_bf16x2(v2, v3);
                ph[ks][2] = pack_bf16x2(w0, w1);
                ph[ks][3] = pack_bf16x2(w2, w3);
                __nv_bfloat162 hh;
                hh = *(__nv_bfloat162*)&ph[ks][0];
                pl[ks][0] = pack_bf16x2(v0 - __bfloat162float(hh.x), v1 - __bfloat162float(hh.y));
                hh = *(__nv_bfloat162*)&ph[ks][1];
                pl[ks][1] = pack_bf16x2(v2 - __bfloat162float(hh.x), v3 - __bfloat162float(hh.y));
                hh = *(__nv_bfloat162*)&ph[ks][2];
                pl[ks][2] = pack_bf16x2(w0 - __bfloat162float(hh.x), w1 - __bfloat162float(hh.y));
                hh = *(__nv_bfloat162*)&ph[ks][3];
                pl[ks][3] = pack_bf16x2(w2 - __bfloat162float(hh.x), w3 - __bfloat162float(hh.y));
            }

#pragma unroll
            for (int ks = 0; ks < 4; ks++) {
#pragma unroll
                for (int db = 0; db < 4; db++) {
                    uint32_t vh4[4], vl4[4];
                    uint32_t a = SWZ((ks * 16 + (lane & 7) + ((lane >> 3) & 1) * 8) * 128 +
                                     ((lane >> 4) + db * 2) * 16);
                    LDSM4T(vh4, sV + a);
                    LDSM4T(vl4, sVl + a);
                    MMA16816(o[db * 2 + 0], ph[ks], vh4[0], vh4[1]);
                    MMA16816(o[db * 2 + 1], ph[ks], vh4[2], vh4[3]);
                    MMA16816(o[db * 2 + 0], ph[ks], vl4[0], vl4[1]);
                    MMA16816(o[db * 2 + 1], ph[ks], vl4[2], vl4[3]);
                    MMA16816(o[db * 2 + 0], pl[ks], vh4[0], vh4[1]);
                    MMA16816(o[db * 2 + 1], pl[ks], vh4[2], vh4[3]);
                }
            }
        }

        __syncthreads();
        if (kc + 2 < nch) {
            ld_kv(kc + 2, kc & 1);
            CP_COMMIT();
        }
    }

    const float i0 = 1.f / l0;
    const float i1 = 1.f / l1;
    const size_t tokA = tok0 + (size_t)qt * 128 + wid * 16 + r0;
#pragma unroll
    for (int j = 0; j < 8; j++) {
        int dc = h * DD + 8 * j + c0;
        float a0 = o[j][0] * i0, a1 = o[j][1] * i0;
        float b0 = o[j][2] * i1, b1 = o[j][3] * i1;
        __nv_bfloat16 h0 = __float2bfloat16(a0), h1 = __float2bfloat16(a1);
        __nv_bfloat16 h2 = __float2bfloat16(b0), h3 = __float2bfloat16(b1);
        size_t offA = tokA * CC + dc;
        size_t offB = (tokA + 8) * CC + dc;
        *(__nv_bfloat162*)(yh + offA) = __nv_bfloat162(h0, h1);
        *(__nv_bfloat162*)(yh + offB) = __nv_bfloat162(h2, h3);
        *(__nv_bfloat162*)(yl + offA) = __nv_bfloat162(
            __float2bfloat16(a0 - __bfloat162float(h0)),
            __float2bfloat16(a1 - __bfloat162float(h1)));
        *(__nv_bfloat162*)(yl + offB) = __nv_bfloat162(
            __float2bfloat16(b0 - __bfloat162float(h2)),
            __float2bfloat16(b1 - __bfloat162float(h3)));
    }
}

// ---------------------------------------------------------------------------
extern "C" void kernel_launch(void* const* d_in, const int* in_sizes, int n_in,
                              void* d_out, int out_size) {
    const float* x      = (const float*)d_in[0];
    const float* w_attn = (const float*)d_in[1];
    const float* w_proj = (const float*)d_in[2];
    float* out = (float*)d_out;

    void *xh_p, *xl_p, *wah_p, *wal_p, *wph_p, *wpl_p, *qh_p, *ql_p, *yh_p, *yl_p;
    cudaGetSymbolAddress(&xh_p, g_xh);
    cudaGetSymbolAddress(&xl_p, g_xl);
    cudaGetSymbolAddress(&wah_p, g_wah);
    cudaGetSymbolAddress(&wal_p, g_wal);
    cudaGetSymbolAddress(&wph_p, g_wph);
    cudaGetSymbolAddress(&wpl_p, g_wpl);
    cudaGetSymbolAddress(&qh_p, g_qkvh);
    cudaGetSymbolAddress(&ql_p, g_qkvl);
    cudaGetSymbolAddress(&yh_p, g_yh);
    cudaGetSymbolAddress(&yl_p, g_yl);

    cudaFuncSetAttribute(gemm_hmma3<true>,
                         cudaFuncAttributeMaxDynamicSharedMemorySize, GEMM_SMEM);
    cudaFuncSetAttribute(gemm_hmma3<false>,
                         cudaFuncAttributeMaxDynamicSharedMemorySize, GEMM_SMEM);
    cudaFuncSetAttribute(attn_hmma,
                         cudaFuncAttributeMaxDynamicSharedMemorySize, ATTN_SMEM);

    // 1) Splits
    split_f32<<<(MM * CC / 4 + 255) / 256, 256>>>(x, (__nv_bfloat16*)xh_p,
                                                  (__nv_bfloat16*)xl_p, MM * CC / 4);
    split_f32<<<(C3 * CC / 4 + 255) / 256, 256>>>(w_attn, (__nv_bfloat16*)wah_p,
                                                  (__nv_bfloat16*)wal_p, C3 * CC / 4);
    split_f32<<<(CC * CC / 4 + 255) / 256, 256>>>(w_proj, (__nv_bfloat16*)wph_p,
                                                  (__nv_bfloat16*)wpl_p, CC * CC / 4);

    // 2) QKV gemm -> bf16 hi/lo planes (q pre-scaled by 1/8)
    gemm_hmma3<true><<<dim3(C3 / 128, MM / 128), 512, GEMM_SMEM>>>(
        (const __nv_bfloat16*)xh_p, (const __nv_bfloat16*)xl_p,
        (const __nv_bfloat16*)wah_p, (const __nv_bfloat16*)wal_p,
        nullptr, (__nv_bfloat16*)qh_p, (__nv_bfloat16*)ql_p, MM, C3, CC);

    // 3) HMMA flash attention -> yh/yl
    attn_hmma<<<dim3(TT / 128, HH, BB), 256, ATTN_SMEM>>>(
        (const __nv_bfloat16*)qh_p, (const __nv_bfloat16*)ql_p,
        (__nv_bfloat16*)yh_p, (__nv_bfloat16*)yl_p);

    // 4) out = y @ w_proj^T (fp32)
    gemm_hmma3<false><<<dim3(CC / 128, MM / 128), 512, GEMM_SMEM>>>(
        (const __nv_bfloat16*)yh_p, (const __nv_bfloat16*)yl_p,
        (const __nv_bfloat16*)wph_p, (const __nv_bfloat16*)wpl_p,
        out, nullptr, nullptr, MM, CC, CC);
}

// round 8
// speedup vs baseline: 1.1225x; 1.1225x over previous
#include <cuda_runtime.h>
#include <cuda_bf16.h>
#include <cstdint>
#include <math.h>

// Problem dims
#define BB 2
#define TT 2048
#define CC 1024
#define HH 16
#define DD 64
#define C3 3072
#define MM (BB * TT)   // 4096

// ---------------------------------------------------------------------------
// Scratch (device globals; no allocation allowed)
// ---------------------------------------------------------------------------
__device__ __nv_bfloat16 g_xh[(size_t)MM * CC];
__device__ __nv_bfloat16 g_xl[(size_t)MM * CC];
__device__ __nv_bfloat16 g_wah[(size_t)C3 * CC];
__device__ __nv_bfloat16 g_wal[(size_t)C3 * CC];
__device__ __nv_bfloat16 g_wph[(size_t)CC * CC];
__device__ __nv_bfloat16 g_wpl[(size_t)CC * CC];
__device__ __nv_bfloat16 g_qkvh[(size_t)MM * C3];
__device__ __nv_bfloat16 g_qkvl[(size_t)MM * C3];
__device__ __nv_bfloat16 g_yh[(size_t)MM * CC];
__device__ __nv_bfloat16 g_yl[(size_t)MM * CC];

// ---------------------------------------------------------------------------
// Helpers (sm_103 base-target: ldmatrix / mma.sync / cp.async)
// ---------------------------------------------------------------------------
__device__ __forceinline__ uint32_t smem_to_u32(const void* p) {
    uint32_t a;
    asm("{ .reg .u64 t; cvta.to.shared.u64 t, %1; cvt.u32.u64 %0, t; }"
        : "=r"(a) : "l"(p));
    return a;
}

#define SWZ(off) ((off) ^ (((off) >> 3) & 0x70))

__device__ __forceinline__ void cp16(uint32_t saddr, const void* g) {
    asm volatile("cp.async.cg.shared.global [%0], [%1], 16;"
                 :: "r"(saddr), "l"(g));
}
#define CP_COMMIT() asm volatile("cp.async.commit_group;" ::: "memory")
#define CP_WAIT(n)  asm volatile("cp.async.wait_group %0;" :: "n"(n) : "memory")

#define LDSM4(r, addr) \
    asm volatile("ldmatrix.sync.aligned.m8n8.x4.shared.b16 {%0,%1,%2,%3}, [%4];" \
        : "=r"((r)[0]), "=r"((r)[1]), "=r"((r)[2]), "=r"((r)[3]) : "r"(addr))

#define LDSM4T(r, addr) \
    asm volatile("ldmatrix.sync.aligned.m8n8.x4.trans.shared.b16 {%0,%1,%2,%3}, [%4];" \
        : "=r"((r)[0]), "=r"((r)[1]), "=r"((r)[2]), "=r"((r)[3]) : "r"(addr))

#define MMA16816(d, a, b0v, b1v) \
    asm volatile("mma.sync.aligned.m16n8k16.row.col.f32.bf16.bf16.f32 " \
        "{%0,%1,%2,%3}, {%4,%5,%6,%7}, {%8,%9}, {%0,%1,%2,%3};" \
        : "+f"((d)[0]), "+f"((d)[1]), "+f"((d)[2]), "+f"((d)[3]) \
        : "r"((a)[0]), "r"((a)[1]), "r"((a)[2]), "r"((a)[3]), "r"(b0v), "r"(b1v))

__device__ __forceinline__ uint32_t pack_bf16x2(float a, float b) {
    __nv_bfloat162 t = __floats2bfloat162_rn(a, b);
    return *(uint32_t*)&t;
}

// ---------------------------------------------------------------------------
// Split fp32 -> bf16 hi/lo planes
// ---------------------------------------------------------------------------
__global__ void __launch_bounds__(256) split_f32(const float* __restrict__ in,
                                                 __nv_bfloat16* __restrict__ hi,
                                                 __nv_bfloat16* __restrict__ lo,
                                                 int n4) {
    int i = blockIdx.x * 256 + threadIdx.x;
    if (i >= n4) return;
    float4 v = ((const float4*)in)[i];
    __nv_bfloat16 h0 = __float2bfloat16(v.x);
    __nv_bfloat16 h1 = __float2bfloat16(v.y);
    __nv_bfloat16 h2 = __float2bfloat16(v.z);
    __nv_bfloat16 h3 = __float2bfloat16(v.w);
    __nv_bfloat16 l0 = __float2bfloat16(v.x - __bfloat162float(h0));
    __nv_bfloat16 l1 = __float2bfloat16(v.y - __bfloat162float(h1));
    __nv_bfloat16 l2 = __float2bfloat16(v.z - __bfloat162float(h2));
    __nv_bfloat16 l3 = __float2bfloat16(v.w - __bfloat162float(h3));
    ((__nv_bfloat162*)hi)[i * 2 + 0] = __nv_bfloat162(h0, h1);
    ((__nv_bfloat162*)hi)[i * 2 + 1] = __nv_bfloat162(h2, h3);
    ((__nv_bfloat162*)lo)[i * 2 + 0] = __nv_bfloat162(l0, l1);
    ((__nv_bfloat162*)lo)[i * 2 + 1] = __nv_bfloat162(l2, l3);
}

// ---------------------------------------------------------------------------
// HMMA GEMM: C[M,N] = A[M,K] @ B[N,K]^T, fp32-accurate via bf16 3-term split.
// Tile 128x128, K-chunk 32, 128 threads (4 warps = 2m x 2n), warp tile 64x64.
// CTA-wide LDSM per k16 halved vs 32x32 warp tiles (fragment reuse x4).
// 3-stage cp.async pipeline @ 96KB smem -> 2 CTAs/SM.
// SPLIT=true: write bf16 hi/lo planes (scaling cols<1024 by 0.125 for Q).
// ---------------------------------------------------------------------------
#define NSTAGE 3
#define STAGE_BYTES 32768
#define GEMM_SMEM (NSTAGE * STAGE_BYTES)   // 98304

template <bool SPLIT>
__global__ void __launch_bounds__(128, 2) gemm_hmma3(
    const __nv_bfloat16* __restrict__ Ah, const __nv_bfloat16* __restrict__ Al,
    const __nv_bfloat16* __restrict__ Bh, const __nv_bfloat16* __restrict__ Bl,
    float* __restrict__ C, __nv_bfloat16* __restrict__ Ch,
    __nv_bfloat16* __restrict__ Cl, int M, int N, int K) {
    extern __shared__ char smem[];
    const uint32_t sbase = smem_to_u32(smem);
    const int tid = threadIdx.x;
    const int lane = tid & 31;
    const int wid = tid >> 5;      // 0..3
    const int wm = wid >> 1;       // 0..1
    const int wn = wid & 1;        // 0..1
    const int bm = blockIdx.y * 128;
    const int bn = blockIdx.x * 128;

    float acc[4][8][4];            // mi(4) x nj(8 = 4nb x 2 halves) x 4
#pragma unroll
    for (int i = 0; i < 4; i++)
#pragma unroll
        for (int j = 0; j < 8; j++)
#pragma unroll
            for (int t = 0; t < 4; t++) acc[i][j][t] = 0.f;

    const int nch = K >> 5;
    const int rowL = tid >> 3;     // 0..15
    const int uL = tid & 7;        // 16B unit: 0-3 hi plane, 4-7 lo plane

    auto ld_chunk = [&](int c, int st) {
        const int k0 = c << 5;
        const uint32_t sA = sbase + st * STAGE_BYTES;
        const uint32_t sB = sA + 16384;
        const int kk = k0 + (uL & 3) * 8;
        const bool isHi = (uL < 4);
        const __nv_bfloat16* gA = (isHi ? Ah : Al);
        const __nv_bfloat16* gB = (isHi ? Bh : Bl);
#pragma unroll
        for (int it = 0; it < 8; it++) {
            int row = rowL + it * 16;
            cp16(sA + SWZ(row * 128 + uL * 16), gA + (size_t)(bm + row) * K + kk);
            cp16(sB + SWZ(row * 128 + uL * 16), gB + (size_t)(bn + row) * K + kk);
        }
    };

    auto compute = [&](int st) {
        const uint32_t sA = sbase + st * STAGE_BYTES;
        const uint32_t sB = sA + 16384;
#pragma unroll
        for (int ks = 0; ks < 2; ks++) {
            uint32_t ah[4][4], al[4][4];
            const int rA = lane & 15;
            const int uA = ks * 2 + (lane >> 4);
#pragma unroll
            for (int mi = 0; mi < 4; mi++) {
                int mrow = wm * 64 + mi * 16 + rA;
                LDSM4(ah[mi], sA + SWZ(mrow * 128 + uA * 16));
                LDSM4(al[mi], sA + SWZ(mrow * 128 + (uA + 4) * 16));
            }
            const int rB = (lane & 7) + ((lane & 16) >> 1);
            const int uB = ks * 2 + ((lane & 8) >> 3);
#pragma unroll
            for (int nb = 0; nb < 4; nb++) {
                int nrow = wn * 64 + nb * 16 + rB;
                uint32_t bh[4], bl[4];
                LDSM4(bh, sB + SWZ(nrow * 128 + uB * 16));
                LDSM4(bl, sB + SWZ(nrow * 128 + (uB + 4) * 16));
#pragma unroll
                for (int mi = 0; mi < 4; mi++) {
                    MMA16816(acc[mi][nb * 2 + 0], ah[mi], bh[0], bh[1]);
                    MMA16816(acc[mi][nb * 2 + 1], ah[mi], bh[2], bh[3]);
                    MMA16816(acc[mi][nb * 2 + 0], ah[mi], bl[0], bl[1]);
                    MMA16816(acc[mi][nb * 2 + 1], ah[mi], bl[2], bl[3]);
                    MMA16816(acc[mi][nb * 2 + 0], al[mi], bh[0], bh[1]);
                    MMA16816(acc[mi][nb * 2 + 1], al[mi], bh[2], bh[3]);
                }
            }
        }
    };

    // 2-deep prologue into 3 stages
    ld_chunk(0, 0); CP_COMMIT();
    ld_chunk(1, 1); CP_COMMIT();

    for (int c = 0; c < nch; c++) {
        if (c + 1 < nch) CP_WAIT(1);
        else             CP_WAIT(0);
        __syncthreads();
        // Issue next load first (stage (c+2)%3 == (c-1)%3, whose readers all
        // finished compute(c-1) before the barrier above).
        if (c + 2 < nch) {
            int st = c + 2;
            ld_chunk(st, st - (st / NSTAGE) * NSTAGE);
            CP_COMMIT();
        }
        compute(c - (c / NSTAGE) * NSTAGE);
    }

    // Epilogue
    const int er = lane >> 2;
    const int ec = (lane & 3) * 2;
    const float sc = (SPLIT && bn < 1024) ? 0.125f : 1.0f;  // fold q scale
#pragma unroll
    for (int mi = 0; mi < 4; mi++) {
#pragma unroll
        for (int nj = 0; nj < 8; nj++) {
            int row = bm + wm * 64 + mi * 16 + er;
            int col = bn + wn * 64 + nj * 8 + ec;
            if (SPLIT) {
#pragma unroll
                for (int rr = 0; rr < 2; rr++) {
                    float a0 = acc[mi][nj][rr * 2 + 0] * sc;
                    float a1 = acc[mi][nj][rr * 2 + 1] * sc;
                    __nv_bfloat16 h0 = __float2bfloat16(a0);
                    __nv_bfloat16 h1 = __float2bfloat16(a1);
                    __nv_bfloat16 l0 = __float2bfloat16(a0 - __bfloat162float(h0));
                    __nv_bfloat16 l1 = __float2bfloat16(a1 - __bfloat162float(h1));
                    size_t off = (size_t)(row + rr * 8) * N + col;
                    *(__nv_bfloat162*)(Ch + off) = __nv_bfloat162(h0, h1);
                    *(__nv_bfloat162*)(Cl + off) = __nv_bfloat162(l0, l1);
                }
            } else {
                float2 v0 = make_float2(acc[mi][nj][0], acc[mi][nj][1]);
                float2 v1 = make_float2(acc[mi][nj][2], acc[mi][nj][3]);
                *(float2*)(C + (size_t)row * N + col) = v0;
                *(float2*)(C + (size_t)(row + 8) * N + col) = v1;
            }
        }
    }
}

// ---------------------------------------------------------------------------
// HMMA flash attention (causal). CTA = 128 q rows, 8 warps (16 rows each).
// Unchanged from round 6 (passes).
// ---------------------------------------------------------------------------
#define AQH 0
#define AQL 16384
#define AST(s) (32768 + (s) * 32768)   // stage: KH +0, KL +8192, VH +16384, VL +24576
#define ATTN_SMEM (32768 + 2 * 32768)  // 98304

__global__ void __launch_bounds__(256) attn_hmma(
    const __nv_bfloat16* __restrict__ qkvh, const __nv_bfloat16* __restrict__ qkvl,
    __nv_bfloat16* __restrict__ yh, __nv_bfloat16* __restrict__ yl) {
    extern __shared__ char smem[];
    const uint32_t sb = smem_to_u32(smem);
    const int qt = blockIdx.x;
    const int h  = blockIdx.y;
    const int b  = blockIdx.z;
    const int tid = threadIdx.x;
    const int lane = tid & 31;
    const int wid = tid >> 5;

    const size_t tok0 = (size_t)b * TT;

    // ---- Q tile load (128 rows x 64 d, hi+lo) ----
    {
        const int u = tid & 7;
        const int r = tid >> 3;
#pragma unroll
        for (int p = 0; p < 2; p++) {
            const __nv_bfloat16* gq =
                (p ? qkvl : qkvh) + (tok0 + (size_t)qt * 128) * C3 + h * DD + u * 8;
            const uint32_t sq = sb + (p ? AQL : AQH);
#pragma unroll
            for (int it = 0; it < 4; it++) {
                int row = r + it * 32;
                cp16(sq + SWZ(row * 128 + u * 16), gq + (size_t)row * C3);
            }
        }
    }

    auto ld_kv = [&](int kc, int st) {
        const int u = tid & 7;
        const int r = tid >> 3;
        const uint32_t sst = sb + AST(st);
        const size_t trow = tok0 + (size_t)kc * 64;
#pragma unroll
        for (int p = 0; p < 4; p++) {   // KH, KL, VH, VL
            const __nv_bfloat16* g = ((p & 1) ? qkvl : qkvh) + trow * C3 +
                                     ((p < 2) ? CC : 2 * CC) + h * DD + u * 8;
            const uint32_t sdst = sst + p * 8192;
#pragma unroll
            for (int it = 0; it < 2; it++) {
                int row = r + it * 32;
                cp16(sdst + SWZ(row * 128 + u * 16), g + (size_t)row * C3);
            }
        }
    };

    const int nch = 2 * qt + 2;
    ld_kv(0, 0);
    CP_COMMIT();
    if (nch > 1) { ld_kv(1, 1); CP_COMMIT(); }

    uint32_t qh[4][4], ql[4][4];
    float o[8][4];
#pragma unroll
    for (int j = 0; j < 8; j++)
#pragma unroll
        for (int t = 0; t < 4; t++) o[j][t] = 0.f;
    float m0 = -1e30f, m1 = -1e30f, l0 = 0.f, l1 = 0.f;

    const int qrow_lo = qt * 128 + wid * 16;
    const int r0 = lane >> 2;
    const int c0 = (lane & 3) * 2;

    for (int kc = 0; kc < nch; kc++) {
        if (kc + 1 < nch) CP_WAIT(1); else CP_WAIT(0);
        __syncthreads();

        if (kc == 0) {
#pragma unroll
            for (int ks = 0; ks < 4; ks++) {
                const int rA = lane & 15;
                const int uA = ks * 2 + (lane >> 4);
                uint32_t a = SWZ((wid * 16 + rA) * 128 + uA * 16);
                LDSM4(qh[ks], sb + AQH + a);
                LDSM4(ql[ks], sb + AQL + a);
            }
        }

        if (kc * 64 <= qrow_lo + 15) {
            const uint32_t sK  = sb + AST(kc & 1);
            const uint32_t sKl = sK + 8192;
            const uint32_t sV  = sK + 16384;
            const uint32_t sVl = sK + 24576;

            float s[8][4];
#pragma unroll
            for (int j = 0; j < 8; j++)
#pragma unroll
                for (int t = 0; t < 4; t++) s[j][t] = 0.f;

            const int rB = (lane & 7) + ((lane & 16) >> 1);
#pragma unroll
            for (int ks = 0; ks < 4; ks++) {
                const int uB = ks * 2 + ((lane & 8) >> 3);
#pragma unroll
                for (int nb = 0; nb < 4; nb++) {
                    uint32_t kh4[4], kl4[4];
                    uint32_t a = SWZ((nb * 16 + rB) * 128 + uB * 16);
                    LDSM4(kh4, sK + a);
                    LDSM4(kl4, sKl + a);
                    MMA16816(s[nb * 2 + 0], qh[ks], kh4[0], kh4[1]);
                    MMA16816(s[nb * 2 + 1], qh[ks], kh4[2], kh4[3]);
                    MMA16816(s[nb * 2 + 0], qh[ks], kl4[0], kl4[1]);
                    MMA16816(s[nb * 2 + 1], qh[ks], kl4[2], kl4[3]);
                    MMA16816(s[nb * 2 + 0], ql[ks], kh4[0], kh4[1]);
                    MMA16816(s[nb * 2 + 1], ql[ks], kh4[2], kh4[3]);
                }
            }

            if (kc * 64 + 63 > qrow_lo) {
                const int qr0 = qrow_lo + r0;
#pragma unroll
                for (int j = 0; j < 8; j++) {
                    int kcol = kc * 64 + 8 * j + c0;
                    if (kcol > qr0)     s[j][0] = -1e30f;
                    if (kcol + 1 > qr0) s[j][1] = -1e30f;
                    if (kcol > qr0 + 8)     s[j][2] = -1e30f;
                    if (kcol + 1 > qr0 + 8) s[j][3] = -1e30f;
                }
            }

            float mx0 = -1e30f, mx1 = -1e30f;
#pragma unroll
            for (int j = 0; j < 8; j++) {
                mx0 = fmaxf(mx0, fmaxf(s[j][0], s[j][1]));
                mx1 = fmaxf(mx1, fmaxf(s[j][2], s[j][3]));
            }
            mx0 = fmaxf(mx0, __shfl_xor_sync(0xffffffffu, mx0, 1));
            mx0 = fmaxf(mx0, __shfl_xor_sync(0xffffffffu, mx0, 2));
            mx1 = fmaxf(mx1, __shfl_xor_sync(0xffffffffu, mx1, 1));
            mx1 = fmaxf(mx1, __shfl_xor_sync(0xffffffffu, mx1, 2));
            float mn0 = fmaxf(m0, mx0);
            float mn1 = fmaxf(m1, mx1);
            float corr0 = __expf(m0 - mn0);
            float corr1 = __expf(m1 - mn1);
            float ls0 = 0.f, ls1 = 0.f;
#pragma unroll
            for (int j = 0; j < 8; j++) {
                s[j][0] = __expf(s[j][0] - mn0);
                s[j][1] = __expf(s[j][1] - mn0);
                s[j][2] = __expf(s[j][2] - mn1);
                s[j][3] = __expf(s[j][3] - mn1);
                ls0 += s[j][0] + s[j][1];
                ls1 += s[j][2] + s[j][3];
            }
            ls0 += __shfl_xor_sync(0xffffffffu, ls0, 1);
            ls0 += __shfl_xor_sync(0xffffffffu, ls0, 2);
            ls1 += __shfl_xor_sync(0xffffffffu, ls1, 1);
            ls1 += __shfl_xor_sync(0xffffffffu, ls1, 2);
            l0 = l0 * corr0 + ls0;
            l1 = l1 * corr1 + ls1;
            m0 = mn0; m1 = mn1;
#pragma unroll
            for (int j = 0; j < 8; j++) {
                o[j][0] *= corr0; o[j][1] *= corr0;
                o[j][2] *= corr1; o[j][3] *= corr1;
            }

            uint32_t ph[4][4], pl[4][4];
#pragma unroll
            for (int ks = 0; ks < 4; ks++) {
                const int j0 = 2 * ks, j1 = 2 * ks + 1;
                float v0 = s[j0][0], v1 = s[j0][1], v2 = s[j0][2], v3 = s[j0][3];
                float w0 = s[j1][0], w1 = s[j1][1], w2 = s[j1][2], w3 = s[j1][3];
                ph[ks][0] = pack_bf16x2(v0, v1);
                ph[ks][1] = pack_bf16x2(v2, v3);
                ph[ks][2] = pack_bf16x2(w0, w1);
                ph[ks][3] = pack_bf16x2(w2, w3);
                __nv_bfloat162 hh;
                hh = *(__nv_bfloat162*)&ph[ks][0];
                pl[ks][0] = pack_bf16x2(v0 - __bfloat162float(hh.x), v1 - __bfloat162float(hh.y));
                hh = *(__nv_bfloat162*)&ph[ks][1];
                pl[ks][1] = pack_bf16x2(v2 - __bfloat162float(hh.x), v3 - __bfloat162float(hh.y));
                hh = *(__nv_bfloat162*)&ph[ks][2];
                pl[ks][2] = pack_bf16x2(w0 - __bfloat162float(hh.x), w1 - __bfloat162float(hh.y));
                hh = *(__nv_bfloat162*)&ph[ks][3];
                pl[ks][3] = pack_bf16x2(w2 - __bfloat162float(hh.x), w3 - __bfloat162float(hh.y));
            }

#pragma unroll
            for (int ks = 0; ks < 4; ks++) {
#pragma unroll
                for (int db = 0; db < 4; db++) {
                    uint32_t vh4[4], vl4[4];
                    uint32_t a = SWZ((ks * 16 + (lane & 7) + ((lane >> 3) & 1) * 8) * 128 +
                                     ((lane >> 4) + db * 2) * 16);
                    LDSM4T(vh4, sV + a);
                    LDSM4T(vl4, sVl + a);
                    MMA16816(o[db * 2 + 0], ph[ks], vh4[0], vh4[1]);
                    MMA16816(o[db * 2 + 1], ph[ks], vh4[2], vh4[3]);
                    MMA16816(o[db * 2 + 0], ph[ks], vl4[0], vl4[1]);
                    MMA16816(o[db * 2 + 1], ph[ks], vl4[2], vl4[3]);
                    MMA16816(o[db * 2 + 0], pl[ks], vh4[0], vh4[1]);
                    MMA16816(o[db * 2 + 1], pl[ks], vh4[2], vh4[3]);
                }
            }
        }

        __syncthreads();
        if (kc + 2 < nch) {
            ld_kv(kc + 2, kc & 1);
            CP_COMMIT();
        }
    }

    const float i0 = 1.f / l0;
    const float i1 = 1.f / l1;
    const size_t tokA = tok0 + (size_t)qt * 128 + wid * 16 + r0;
#pragma unroll
    for (int j = 0; j < 8; j++) {
        int dc = h * DD + 8 * j + c0;
        float a0 = o[j][0] * i0, a1 = o[j][1] * i0;
        float b0 = o[j][2] * i1, b1 = o[j][3] * i1;
        __nv_bfloat16 h0 = __float2bfloat16(a0), h1 = __float2bfloat16(a1);
        __nv_bfloat16 h2 = __float2bfloat16(b0), h3 = __float2bfloat16(b1);
        size_t offA = tokA * CC + dc;
        size_t offB = (tokA + 8) * CC + dc;
        *(__nv_bfloat162*)(yh + offA) = __nv_bfloat162(h0, h1);
        *(__nv_bfloat162*)(yh + offB) = __nv_bfloat162(h2, h3);
        *(__nv_bfloat162*)(yl + offA) = __nv_bfloat162(
            __float2bfloat16(a0 - __bfloat162float(h0)),
            __float2bfloat16(a1 - __bfloat162float(h1)));
        *(__nv_bfloat162*)(yl + offB) = __nv_bfloat162(
            __float2bfloat16(b0 - __bfloat162float(h2)),
            __float2bfloat16(b1 - __bfloat162float(h3)));
    }
}

// ---------------------------------------------------------------------------
extern "C" void kernel_launch(void* const* d_in, const int* in_sizes, int n_in,
                              void* d_out, int out_size) {
    const float* x      = (const float*)d_in[0];
    const float* w_attn = (const float*)d_in[1];
    const float* w_proj = (const float*)d_in[2];
    float* out = (float*)d_out;

    void *xh_p, *xl_p, *wah_p, *wal_p, *wph_p, *wpl_p, *qh_p, *ql_p, *yh_p, *yl_p;
    cudaGetSymbolAddress(&xh_p, g_xh);
    cudaGetSymbolAddress(&xl_p, g_xl);
    cudaGetSymbolAddress(&wah_p, g_wah);
    cudaGetSymbolAddress(&wal_p, g_wal);
    cudaGetSymbolAddress(&wph_p, g_wph);
    cudaGetSymbolAddress(&wpl_p, g_wpl);
    cudaGetSymbolAddress(&qh_p, g_qkvh);
    cudaGetSymbolAddress(&ql_p, g_qkvl);
    cudaGetSymbolAddress(&yh_p, g_yh);
    cudaGetSymbolAddress(&yl_p, g_yl);

    cudaFuncSetAttribute(gemm_hmma3<true>,
                         cudaFuncAttributeMaxDynamicSharedMemorySize, GEMM_SMEM);
    cudaFuncSetAttribute(gemm_hmma3<false>,
                         cudaFuncAttributeMaxDynamicSharedMemorySize, GEMM_SMEM);
    cudaFuncSetAttribute(attn_hmma,
                         cudaFuncAttributeMaxDynamicSharedMemorySize, ATTN_SMEM);

    // 1) Splits
    split_f32<<<(MM * CC / 4 + 255) / 256, 256>>>(x, (__nv_bfloat16*)xh_p,
                                                  (__nv_bfloat16*)xl_p, MM * CC / 4);
    split_f32<<<(C3 * CC / 4 + 255) / 256, 256>>>(w_attn, (__nv_bfloat16*)wah_p,
                                                  (__nv_bfloat16*)wal_p, C3 * CC / 4);
    split_f32<<<(CC * CC / 4 + 255) / 256, 256>>>(w_proj, (__nv_bfloat16*)wph_p,
                                                  (__nv_bfloat16*)wpl_p, CC * CC / 4);

    // 2) QKV gemm -> bf16 hi/lo planes (q pre-scaled by 1/8)
    gemm_hmma3<true><<<dim3(C3 / 128, MM / 128), 128, GEMM_SMEM>>>(
        (const __nv_bfloat16*)xh_p, (const __nv_bfloat16*)xl_p,
        (const __nv_bfloat16*)wah_p, (const __nv_bfloat16*)wal_p,
        nullptr, (__nv_bfloat16*)qh_p, (__nv_bfloat16*)ql_p, MM, C3, CC);

    // 3) HMMA flash attention -> yh/yl
    attn_hmma<<<dim3(TT / 128, HH, BB), 256, ATTN_SMEM>>>(
        (const __nv_bfloat16*)qh_p, (const __nv_bfloat16*)ql_p,
        (__nv_bfloat16*)yh_p, (__nv_bfloat16*)yl_p);

    // 4) out = y @ w_proj^T (fp32)
    gemm_hmma3<false><<<dim3(CC / 128, MM / 128), 128, GEMM_SMEM>>>(
        (const __nv_bfloat16*)yh_p, (const __nv_bfloat16*)yl_p,
        (const __nv_bfloat16*)wph_p, (const __nv_bfloat16*)wpl_p,
        out, nullptr, nullptr, MM, CC, CC);
}

// round 9
// speedup vs baseline: 1.1416x; 1.0170x over previous
#include <cuda_runtime.h>
#include <cuda_bf16.h>
#include <cstdint>
#include <math.h>

// Problem dims
#define BB 2
#define TT 2048
#define CC 1024
#define HH 16
#define DD 64
#define C3 3072
#define MM (BB * TT)   // 4096

// ---------------------------------------------------------------------------
// Scratch (device globals; no allocation allowed)
// ---------------------------------------------------------------------------
__device__ __nv_bfloat16 g_xh[(size_t)MM * CC];
__device__ __nv_bfloat16 g_xl[(size_t)MM * CC];
__device__ __nv_bfloat16 g_wah[(size_t)C3 * CC];
__device__ __nv_bfloat16 g_wal[(size_t)C3 * CC];
__device__ __nv_bfloat16 g_wph[(size_t)CC * CC];
__device__ __nv_bfloat16 g_wpl[(size_t)CC * CC];
__device__ __nv_bfloat16 g_qkvh[(size_t)MM * C3];
__device__ __nv_bfloat16 g_qkvl[(size_t)MM * C3];
__device__ __nv_bfloat16 g_yh[(size_t)MM * CC];
__device__ __nv_bfloat16 g_yl[(size_t)MM * CC];

// ---------------------------------------------------------------------------
// Helpers (sm_103 base-target: ldmatrix / mma.sync / cp.async)
// ---------------------------------------------------------------------------
__device__ __forceinline__ uint32_t smem_to_u32(const void* p) {
    uint32_t a;
    asm("{ .reg .u64 t; cvta.to.shared.u64 t, %1; cvt.u32.u64 %0, t; }"
        : "=r"(a) : "l"(p));
    return a;
}

#define SWZ(off) ((off) ^ (((off) >> 3) & 0x70))

__device__ __forceinline__ void cp16(uint32_t saddr, const void* g) {
    asm volatile("cp.async.cg.shared.global [%0], [%1], 16;"
                 :: "r"(saddr), "l"(g));
}
#define CP_COMMIT() asm volatile("cp.async.commit_group;" ::: "memory")
#define CP_WAIT(n)  asm volatile("cp.async.wait_group %0;" :: "n"(n) : "memory")

#define LDSM4(r, addr) \
    asm volatile("ldmatrix.sync.aligned.m8n8.x4.shared.b16 {%0,%1,%2,%3}, [%4];" \
        : "=r"((r)[0]), "=r"((r)[1]), "=r"((r)[2]), "=r"((r)[3]) : "r"(addr))

#define LDSM4T(r, addr) \
    asm volatile("ldmatrix.sync.aligned.m8n8.x4.trans.shared.b16 {%0,%1,%2,%3}, [%4];" \
        : "=r"((r)[0]), "=r"((r)[1]), "=r"((r)[2]), "=r"((r)[3]) : "r"(addr))

#define MMA16816(d, a, b0v, b1v) \
    asm volatile("mma.sync.aligned.m16n8k16.row.col.f32.bf16.bf16.f32 " \
        "{%0,%1,%2,%3}, {%4,%5,%6,%7}, {%8,%9}, {%0,%1,%2,%3};" \
        : "+f"((d)[0]), "+f"((d)[1]), "+f"((d)[2]), "+f"((d)[3]) \
        : "r"((a)[0]), "r"((a)[1]), "r"((a)[2]), "r"((a)[3]), "r"(b0v), "r"(b1v))

__device__ __forceinline__ uint32_t pack_bf16x2(float a, float b) {
    __nv_bfloat162 t = __floats2bfloat162_rn(a, b);
    return *(uint32_t*)&t;
}

// ---------------------------------------------------------------------------
// Split fp32 -> bf16 hi/lo planes
// ---------------------------------------------------------------------------
__global__ void __launch_bounds__(256) split_f32(const float* __restrict__ in,
                                                 __nv_bfloat16* __restrict__ hi,
                                                 __nv_bfloat16* __restrict__ lo,
                                                 int n4) {
    int i = blockIdx.x * 256 + threadIdx.x;
    if (i >= n4) return;
    float4 v = ((const float4*)in)[i];
    __nv_bfloat16 h0 = __float2bfloat16(v.x);
    __nv_bfloat16 h1 = __float2bfloat16(v.y);
    __nv_bfloat16 h2 = __float2bfloat16(v.z);
    __nv_bfloat16 h3 = __float2bfloat16(v.w);
    __nv_bfloat16 l0 = __float2bfloat16(v.x - __bfloat162float(h0));
    __nv_bfloat16 l1 = __float2bfloat16(v.y - __bfloat162float(h1));
    __nv_bfloat16 l2 = __float2bfloat16(v.z - __bfloat162float(h2));
    __nv_bfloat16 l3 = __float2bfloat16(v.w - __bfloat162float(h3));
    ((__nv_bfloat162*)hi)[i * 2 + 0] = __nv_bfloat162(h0, h1);
    ((__nv_bfloat162*)hi)[i * 2 + 1] = __nv_bfloat162(h2, h3);
    ((__nv_bfloat162*)lo)[i * 2 + 0] = __nv_bfloat162(l0, l1);
    ((__nv_bfloat162*)lo)[i * 2 + 1] = __nv_bfloat162(l2, l3);
}

// ---------------------------------------------------------------------------
// HMMA GEMM — unchanged from round 8 (tensor 60.6%, protect the win).
// Tile 128x128, K-chunk 32, 128 threads (4 warps = 2m x 2n), warp tile 64x64.
// ---------------------------------------------------------------------------
#define NSTAGE 3
#define STAGE_BYTES 32768
#define GEMM_SMEM (NSTAGE * STAGE_BYTES)   // 98304

template <bool SPLIT>
__global__ void __launch_bounds__(128, 2) gemm_hmma3(
    const __nv_bfloat16* __restrict__ Ah, const __nv_bfloat16* __restrict__ Al,
    const __nv_bfloat16* __restrict__ Bh, const __nv_bfloat16* __restrict__ Bl,
    float* __restrict__ C, __nv_bfloat16* __restrict__ Ch,
    __nv_bfloat16* __restrict__ Cl, int M, int N, int K) {
    extern __shared__ char smem[];
    const uint32_t sbase = smem_to_u32(smem);
    const int tid = threadIdx.x;
    const int lane = tid & 31;
    const int wid = tid >> 5;      // 0..3
    const int wm = wid >> 1;       // 0..1
    const int wn = wid & 1;        // 0..1
    const int bm = blockIdx.y * 128;
    const int bn = blockIdx.x * 128;

    float acc[4][8][4];
#pragma unroll
    for (int i = 0; i < 4; i++)
#pragma unroll
        for (int j = 0; j < 8; j++)
#pragma unroll
            for (int t = 0; t < 4; t++) acc[i][j][t] = 0.f;

    const int nch = K >> 5;
    const int rowL = tid >> 3;     // 0..15
    const int uL = tid & 7;

    auto ld_chunk = [&](int c, int st) {
        const int k0 = c << 5;
        const uint32_t sA = sbase + st * STAGE_BYTES;
        const uint32_t sB = sA + 16384;
        const int kk = k0 + (uL & 3) * 8;
        const bool isHi = (uL < 4);
        const __nv_bfloat16* gA = (isHi ? Ah : Al);
        const __nv_bfloat16* gB = (isHi ? Bh : Bl);
#pragma unroll
        for (int it = 0; it < 8; it++) {
            int row = rowL + it * 16;
            cp16(sA + SWZ(row * 128 + uL * 16), gA + (size_t)(bm + row) * K + kk);
            cp16(sB + SWZ(row * 128 + uL * 16), gB + (size_t)(bn + row) * K + kk);
        }
    };

    auto compute = [&](int st) {
        const uint32_t sA = sbase + st * STAGE_BYTES;
        const uint32_t sB = sA + 16384;
#pragma unroll
        for (int ks = 0; ks < 2; ks++) {
            uint32_t ah[4][4], al[4][4];
            const int rA = lane & 15;
            const int uA = ks * 2 + (lane >> 4);
#pragma unroll
            for (int mi = 0; mi < 4; mi++) {
                int mrow = wm * 64 + mi * 16 + rA;
                LDSM4(ah[mi], sA + SWZ(mrow * 128 + uA * 16));
                LDSM4(al[mi], sA + SWZ(mrow * 128 + (uA + 4) * 16));
            }
            const int rB = (lane & 7) + ((lane & 16) >> 1);
            const int uB = ks * 2 + ((lane & 8) >> 3);
#pragma unroll
            for (int nb = 0; nb < 4; nb++) {
                int nrow = wn * 64 + nb * 16 + rB;
                uint32_t bh[4], bl[4];
                LDSM4(bh, sB + SWZ(nrow * 128 + uB * 16));
                LDSM4(bl, sB + SWZ(nrow * 128 + (uB + 4) * 16));
#pragma unroll
                for (int mi = 0; mi < 4; mi++) {
                    MMA16816(acc[mi][nb * 2 + 0], ah[mi], bh[0], bh[1]);
                    MMA16816(acc[mi][nb * 2 + 1], ah[mi], bh[2], bh[3]);
                    MMA16816(acc[mi][nb * 2 + 0], ah[mi], bl[0], bl[1]);
                    MMA16816(acc[mi][nb * 2 + 1], ah[mi], bl[2], bl[3]);
                    MMA16816(acc[mi][nb * 2 + 0], al[mi], bh[0], bh[1]);
                    MMA16816(acc[mi][nb * 2 + 1], al[mi], bh[2], bh[3]);
                }
            }
        }
    };

    ld_chunk(0, 0); CP_COMMIT();
    ld_chunk(1, 1); CP_COMMIT();

    for (int c = 0; c < nch; c++) {
        if (c + 1 < nch) CP_WAIT(1);
        else             CP_WAIT(0);
        __syncthreads();
        if (c + 2 < nch) {
            int st = c + 2;
            ld_chunk(st, st - (st / NSTAGE) * NSTAGE);
            CP_COMMIT();
        }
        compute(c - (c / NSTAGE) * NSTAGE);
    }

    const int er = lane >> 2;
    const int ec = (lane & 3) * 2;
    const float sc = (SPLIT && bn < 1024) ? 0.125f : 1.0f;
#pragma unroll
    for (int mi = 0; mi < 4; mi++) {
#pragma unroll
        for (int nj = 0; nj < 8; nj++) {
            int row = bm + wm * 64 + mi * 16 + er;
            int col = bn + wn * 64 + nj * 8 + ec;
            if (SPLIT) {
#pragma unroll
                for (int rr = 0; rr < 2; rr++) {
                    float a0 = acc[mi][nj][rr * 2 + 0] * sc;
                    float a1 = acc[mi][nj][rr * 2 + 1] * sc;
                    __nv_bfloat16 h0 = __float2bfloat16(a0);
                    __nv_bfloat16 h1 = __float2bfloat16(a1);
                    __nv_bfloat16 l0 = __float2bfloat16(a0 - __bfloat162float(h0));
                    __nv_bfloat16 l1 = __float2bfloat16(a1 - __bfloat162float(h1));
                    size_t off = (size_t)(row + rr * 8) * N + col;
                    *(__nv_bfloat162*)(Ch + off) = __nv_bfloat162(h0, h1);
                    *(__nv_bfloat162*)(Cl + off) = __nv_bfloat162(l0, l1);
                }
            } else {
                float2 v0 = make_float2(acc[mi][nj][0], acc[mi][nj][1]);
                float2 v1 = make_float2(acc[mi][nj][2], acc[mi][nj][3]);
                *(float2*)(C + (size_t)row * N + col) = v0;
                *(float2*)(C + (size_t)(row + 8) * N + col) = v1;
            }
        }
    }
}

// ---------------------------------------------------------------------------
// HMMA flash attention (causal). CTA = 128 q rows, 4 warps (32 rows each).
// Each K/V fragment pair now feeds 12 MMAs (was 6) -> LDSM pressure halved.
// K/V chunks of 64 keys, double-buffered cp.async. 128 threads.
// ---------------------------------------------------------------------------
#define AQH 0
#define AQL 16384
#define AST(s) (32768 + (s) * 32768)   // stage: KH +0, KL +8192, VH +16384, VL +24576
#define ATTN_SMEM (32768 + 2 * 32768)  // 98304

__global__ void __launch_bounds__(128) attn_hmma(
    const __nv_bfloat16* __restrict__ qkvh, const __nv_bfloat16* __restrict__ qkvl,
    __nv_bfloat16* __restrict__ yh, __nv_bfloat16* __restrict__ yl) {
    extern __shared__ char smem[];
    const uint32_t sb = smem_to_u32(smem);
    const int qt = blockIdx.x;
    const int h  = blockIdx.y;
    const int b  = blockIdx.z;
    const int tid = threadIdx.x;
    const int lane = tid & 31;
    const int wid = tid >> 5;      // 0..3, each warp owns 32 q rows

    const size_t tok0 = (size_t)b * TT;

    // ---- Q tile load (128 rows x 64 d, hi+lo) ----
    {
        const int u = tid & 7;
        const int r = tid >> 3;    // 0..15
#pragma unroll
        for (int p = 0; p < 2; p++) {
            const __nv_bfloat16* gq =
                (p ? qkvl : qkvh) + (tok0 + (size_t)qt * 128) * C3 + h * DD + u * 8;
            const uint32_t sq = sb + (p ? AQL : AQH);
#pragma unroll
            for (int it = 0; it < 8; it++) {
                int row = r + it * 16;
                cp16(sq + SWZ(row * 128 + u * 16), gq + (size_t)row * C3);
            }
        }
    }

    auto ld_kv = [&](int kc, int st) {
        const int u = tid & 7;
        const int r = tid >> 3;    // 0..15
        const uint32_t sst = sb + AST(st);
        const size_t trow = tok0 + (size_t)kc * 64;
#pragma unroll
        for (int p = 0; p < 4; p++) {   // KH, KL, VH, VL
            const __nv_bfloat16* g = ((p & 1) ? qkvl : qkvh) + trow * C3 +
                                     ((p < 2) ? CC : 2 * CC) + h * DD + u * 8;
            const uint32_t sdst = sst + p * 8192;
#pragma unroll
            for (int it = 0; it < 4; it++) {
                int row = r + it * 16;
                cp16(sdst + SWZ(row * 128 + u * 16), g + (size_t)row * C3);
            }
        }
    };

    const int nch = 2 * qt + 2;
    ld_kv(0, 0);
    CP_COMMIT();
    if (nch > 1) { ld_kv(1, 1); CP_COMMIT(); }

    uint32_t qh[2][4][4], ql[2][4][4];
    float o[2][8][4];
#pragma unroll
    for (int mi = 0; mi < 2; mi++)
#pragma unroll
        for (int j = 0; j < 8; j++)
#pragma unroll
            for (int t = 0; t < 4; t++) o[mi][j][t] = 0.f;
    float mm0[2] = {-1e30f, -1e30f}, mm1[2] = {-1e30f, -1e30f};
    float ll0[2] = {0.f, 0.f},       ll1[2] = {0.f, 0.f};

    const int qrow_lo = qt * 128 + wid * 32;          // warp's first q row
    const int r0 = lane >> 2;
    const int c0 = (lane & 3) * 2;

    for (int kc = 0; kc < nch; kc++) {
        if (kc + 1 < nch) CP_WAIT(1); else CP_WAIT(0);
        __syncthreads();

        if (kc == 0) {
            // Q fragments (persistent): 2 mi blocks of 16 rows
#pragma unroll
            for (int mi = 0; mi < 2; mi++) {
#pragma unroll
                for (int ks = 0; ks < 4; ks++) {
                    const int rA = lane & 15;
                    const int uA = ks * 2 + (lane >> 4);
                    uint32_t a = SWZ((wid * 32 + mi * 16 + rA) * 128 + uA * 16);
                    LDSM4(qh[mi][ks], sb + AQH + a);
                    LDSM4(ql[mi][ks], sb + AQL + a);
                }
            }
        }

        if (kc * 64 <= qrow_lo + 31) {
            const uint32_t sK  = sb + AST(kc & 1);
            const uint32_t sKl = sK + 8192;
            const uint32_t sV  = sK + 16384;
            const uint32_t sVl = sK + 24576;

            // ---- S = Q @ K^T ----
            float s[2][8][4];
#pragma unroll
            for (int mi = 0; mi < 2; mi++)
#pragma unroll
                for (int j = 0; j < 8; j++)
#pragma unroll
                    for (int t = 0; t < 4; t++) s[mi][j][t] = 0.f;

            const int rB = (lane & 7) + ((lane & 16) >> 1);
#pragma unroll
            for (int ks = 0; ks < 4; ks++) {
                const int uB = ks * 2 + ((lane & 8) >> 3);
#pragma unroll
                for (int nb = 0; nb < 4; nb++) {
                    uint32_t kh4[4], kl4[4];
                    uint32_t a = SWZ((nb * 16 + rB) * 128 + uB * 16);
                    LDSM4(kh4, sK + a);
                    LDSM4(kl4, sKl + a);
#pragma unroll
                    for (int mi = 0; mi < 2; mi++) {
                        MMA16816(s[mi][nb * 2 + 0], qh[mi][ks], kh4[0], kh4[1]);
                        MMA16816(s[mi][nb * 2 + 1], qh[mi][ks], kh4[2], kh4[3]);
                        MMA16816(s[mi][nb * 2 + 0], qh[mi][ks], kl4[0], kl4[1]);
                        MMA16816(s[mi][nb * 2 + 1], qh[mi][ks], kl4[2], kl4[3]);
                        MMA16816(s[mi][nb * 2 + 0], ql[mi][ks], kh4[0], kh4[1]);
                        MMA16816(s[mi][nb * 2 + 1], ql[mi][ks], kh4[2], kh4[3]);
                    }
                }
            }

            // ---- causal mask (near diagonal only) ----
            if (kc * 64 + 63 > qrow_lo) {
#pragma unroll
                for (int mi = 0; mi < 2; mi++) {
                    const int qr0 = qrow_lo + mi * 16 + r0;
#pragma unroll
                    for (int j = 0; j < 8; j++) {
                        int kcol = kc * 64 + 8 * j + c0;
                        if (kcol > qr0)         s[mi][j][0] = -1e30f;
                        if (kcol + 1 > qr0)     s[mi][j][1] = -1e30f;
                        if (kcol > qr0 + 8)     s[mi][j][2] = -1e30f;
                        if (kcol + 1 > qr0 + 8) s[mi][j][3] = -1e30f;
                    }
                }
            }

            // ---- online softmax + pack P + O matmul, per mi ----
            uint32_t ph[2][4][4], pl[2][4][4];
#pragma unroll
            for (int mi = 0; mi < 2; mi++) {
                float mx0 = -1e30f, mx1 = -1e30f;
#pragma unroll
                for (int j = 0; j < 8; j++) {
                    mx0 = fmaxf(mx0, fmaxf(s[mi][j][0], s[mi][j][1]));
                    mx1 = fmaxf(mx1, fmaxf(s[mi][j][2], s[mi][j][3]));
                }
                mx0 = fmaxf(mx0, __shfl_xor_sync(0xffffffffu, mx0, 1));
                mx0 = fmaxf(mx0, __shfl_xor_sync(0xffffffffu, mx0, 2));
                mx1 = fmaxf(mx1, __shfl_xor_sync(0xffffffffu, mx1, 1));
                mx1 = fmaxf(mx1, __shfl_xor_sync(0xffffffffu, mx1, 2));
                float mn0 = fmaxf(mm0[mi], mx0);
                float mn1 = fmaxf(mm1[mi], mx1);
                float corr0 = __expf(mm0[mi] - mn0);
                float corr1 = __expf(mm1[mi] - mn1);
                float ls0 = 0.f, ls1 = 0.f;
#pragma unroll
                for (int j = 0; j < 8; j++) {
                    s[mi][j][0] = __expf(s[mi][j][0] - mn0);
                    s[mi][j][1] = __expf(s[mi][j][1] - mn0);
                    s[mi][j][2] = __expf(s[mi][j][2] - mn1);
                    s[mi][j][3] = __expf(s[mi][j][3] - mn1);
                    ls0 += s[mi][j][0] + s[mi][j][1];
                    ls1 += s[mi][j][2] + s[mi][j][3];
                }
                ls0 += __shfl_xor_sync(0xffffffffu, ls0, 1);
                ls0 += __shfl_xor_sync(0xffffffffu, ls0, 2);
                ls1 += __shfl_xor_sync(0xffffffffu, ls1, 1);
                ls1 += __shfl_xor_sync(0xffffffffu, ls1, 2);
                ll0[mi] = ll0[mi] * corr0 + ls0;
                ll1[mi] = ll1[mi] * corr1 + ls1;
                mm0[mi] = mn0; mm1[mi] = mn1;
#pragma unroll
                for (int j = 0; j < 8; j++) {
                    o[mi][j][0] *= corr0; o[mi][j][1] *= corr0;
                    o[mi][j][2] *= corr1; o[mi][j][3] *= corr1;
                }
#pragma unroll
                for (int ks = 0; ks < 4; ks++) {
                    const int j0 = 2 * ks, j1 = 2 * ks + 1;
                    float v0 = s[mi][j0][0], v1 = s[mi][j0][1];
                    float v2 = s[mi][j0][2], v3 = s[mi][j0][3];
                    float w0 = s[mi][j1][0], w1 = s[mi][j1][1];
                    float w2 = s[mi][j1][2], w3 = s[mi][j1][3];
                    ph[mi][ks][0] = pack_bf16x2(v0, v1);
                    ph[mi][ks][1] = pack_bf16x2(v2, v3);
                    ph[mi][ks][2] = pack_bf16x2(w0, w1);
                    ph[mi][ks][3] = pack_bf16x2(w2, w3);
                    __nv_bfloat162 hh;
                    hh = *(__nv_bfloat162*)&ph[mi][ks][0];
                    pl[mi][ks][0] = pack_bf16x2(v0 - __bfloat162float(hh.x),
                                                v1 - __bfloat162float(hh.y));
                    hh = *(__nv_bfloat162*)&ph[mi][ks][1];
                    pl[mi][ks][1] = pack_bf16x2(v2 - __bfloat162float(hh.x),
                                                v3 - __bfloat162float(hh.y));
                    hh = *(__nv_bfloat162*)&ph[mi][ks][2];
                    pl[mi][ks][2] = pack_bf16x2(w0 - __bfloat162float(hh.x),
                                                w1 - __bfloat162float(hh.y));
                    hh = *(__nv_bfloat162*)&ph[mi][ks][3];
                    pl[mi][ks][3] = pack_bf16x2(w2 - __bfloat162float(hh.x),
                                                w3 - __bfloat162float(hh.y));
                }
            }

            // ---- O += P @ V (V^T fragments via ldmatrix.trans) ----
#pragma unroll
            for (int ks = 0; ks < 4; ks++) {
#pragma unroll
                for (int db = 0; db < 4; db++) {
                    uint32_t vh4[4], vl4[4];
                    uint32_t a = SWZ((ks * 16 + (lane & 7) + ((lane >> 3) & 1) * 8) * 128 +
                                     ((lane >> 4) + db * 2) * 16);
                    LDSM4T(vh4, sV + a);
                    LDSM4T(vl4, sVl + a);
#pragma unroll
                    for (int mi = 0; mi < 2; mi++) {
                        MMA16816(o[mi][db * 2 + 0], ph[mi][ks], vh4[0], vh4[1]);
                        MMA16816(o[mi][db * 2 + 1], ph[mi][ks], vh4[2], vh4[3]);
                        MMA16816(o[mi][db * 2 + 0], ph[mi][ks], vl4[0], vl4[1]);
                        MMA16816(o[mi][db * 2 + 1], ph[mi][ks], vl4[2], vl4[3]);
                        MMA16816(o[mi][db * 2 + 0], pl[mi][ks], vh4[0], vh4[1]);
                        MMA16816(o[mi][db * 2 + 1], pl[mi][ks], vh4[2], vh4[3]);
                    }
                }
            }
        }

        __syncthreads();
        if (kc + 2 < nch) {
            ld_kv(kc + 2, kc & 1);
            CP_COMMIT();
        }
    }

    // ---- epilogue: normalize, split hi/lo, write yh/yl ----
#pragma unroll
    for (int mi = 0; mi < 2; mi++) {
        const float i0 = 1.f / ll0[mi];
        const float i1 = 1.f / ll1[mi];
        const size_t tokA = tok0 + (size_t)qt * 128 + wid * 32 + mi * 16 + r0;
#pragma unroll
        for (int j = 0; j < 8; j++) {
            int dc = h * DD + 8 * j + c0;
            float a0 = o[mi][j][0] * i0, a1 = o[mi][j][1] * i0;
            float b0 = o[mi][j][2] * i1, b1 = o[mi][j][3] * i1;
            __nv_bfloat16 h0 = __float2bfloat16(a0), h1 = __float2bfloat16(a1);
            __nv_bfloat16 h2 = __float2bfloat16(b0), h3 = __float2bfloat16(b1);
            size_t offA = tokA * CC + dc;
            size_t offB = (tokA + 8) * CC + dc;
            *(__nv_bfloat162*)(yh + offA) = __nv_bfloat162(h0, h1);
            *(__nv_bfloat162*)(yh + offB) = __nv_bfloat162(h2, h3);
            *(__nv_bfloat162*)(yl + offA) = __nv_bfloat162(
                __float2bfloat16(a0 - __bfloat162float(h0)),
                __float2bfloat16(a1 - __bfloat162float(h1)));
            *(__nv_bfloat162*)(yl + offB) = __nv_bfloat162(
                __float2bfloat16(b0 - __bfloat162float(h2)),
                __float2bfloat16(b1 - __bfloat162float(h3)));
        }
    }
}

// ---------------------------------------------------------------------------
extern "C" void kernel_launch(void* const* d_in, const int* in_sizes, int n_in,
                              void* d_out, int out_size) {
    const float* x      = (const float*)d_in[0];
    const float* w_attn = (const float*)d_in[1];
    const float* w_proj = (const float*)d_in[2];
    float* out = (float*)d_out;

    void *xh_p, *xl_p, *wah_p, *wal_p, *wph_p, *wpl_p, *qh_p, *ql_p, *yh_p, *yl_p;
    cudaGetSymbolAddress(&xh_p, g_xh);
    cudaGetSymbolAddress(&xl_p, g_xl);
    cudaGetSymbolAddress(&wah_p, g_wah);
    cudaGetSymbolAddress(&wal_p, g_wal);
    cudaGetSymbolAddress(&wph_p, g_wph);
    cudaGetSymbolAddress(&wpl_p, g_wpl);
    cudaGetSymbolAddress(&qh_p, g_qkvh);
    cudaGetSymbolAddress(&ql_p, g_qkvl);
    cudaGetSymbolAddress(&yh_p, g_yh);
    cudaGetSymbolAddress(&yl_p, g_yl);

    cudaFuncSetAttribute(gemm_hmma3<true>,
                         cudaFuncAttributeMaxDynamicSharedMemorySize, GEMM_SMEM);
    cudaFuncSetAttribute(gemm_hmma3<false>,
                         cudaFuncAttributeMaxDynamicSharedMemorySize, GEMM_SMEM);
    cudaFuncSetAttribute(attn_hmma,
                         cudaFuncAttributeMaxDynamicSharedMemorySize, ATTN_SMEM);

    // 1) Splits
    split_f32<<<(MM * CC / 4 + 255) / 256, 256>>>(x, (__nv_bfloat16*)xh_p,
                                                  (__nv_bfloat16*)xl_p, MM * CC / 4);
    split_f32<<<(C3 * CC / 4 + 255) / 256, 256>>>(w_attn, (__nv_bfloat16*)wah_p,
                                                  (__nv_bfloat16*)wal_p, C3 * CC / 4);
    split_f32<<<(CC * CC / 4 + 255) / 256, 256>>>(w_proj, (__nv_bfloat16*)wph_p,
                                                  (__nv_bfloat16*)wpl_p, CC * CC / 4);

    // 2) QKV gemm -> bf16 hi/lo planes (q pre-scaled by 1/8)
    gemm_hmma3<true><<<dim3(C3 / 128, MM / 128), 128, GEMM_SMEM>>>(
        (const __nv_bfloat16*)xh_p, (const __nv_bfloat16*)xl_p,
        (const __nv_bfloat16*)wah_p, (const __nv_bfloat16*)wal_p,
        nullptr, (__nv_bfloat16*)qh_p, (__nv_bfloat16*)ql_p, MM, C3, CC);

    // 3) HMMA flash attention -> yh/yl (128 threads, 4 warps x 32 q rows)
    attn_hmma<<<dim3(TT / 128, HH, BB), 128, ATTN_SMEM>>>(
        (const __nv_bfloat16*)qh_p, (const __nv_bfloat16*)ql_p,
        (__nv_bfloat16*)yh_p, (__nv_bfloat16*)yl_p);

    // 4) out = y @ w_proj^T (fp32)
    gemm_hmma3<false><<<dim3(CC / 128, MM / 128), 128, GEMM_SMEM>>>(
        (const __nv_bfloat16*)yh_p, (const __nv_bfloat16*)yl_p,
        (const __nv_bfloat16*)wph_p, (const __nv_bfloat16*)wpl_p,
        out, nullptr, nullptr, MM, CC, CC);
}

// round 10
// speedup vs baseline: 1.6765x; 1.4686x over previous
#include <cuda_runtime.h>
#include <cuda_fp16.h>
#include <cstdint>
#include <math.h>

// Problem dims
#define BB 2
#define TT 2048
#define CC 1024
#define HH 16
#define DD 64
#define C3 3072
#define MM (BB * TT)   // 4096

// ---------------------------------------------------------------------------
// Scratch (device globals; no allocation allowed)
// ---------------------------------------------------------------------------
__device__ __half g_xh[(size_t)MM * CC];
__device__ __half g_xl[(size_t)MM * CC];
__device__ __half g_wah[(size_t)C3 * CC];
__device__ __half g_wph[(size_t)CC * CC];
__device__ __half g_qkvh[(size_t)MM * C3];
__device__ __half g_qkvl[(size_t)MM * C3];   // lo only used/written for q cols
__device__ __half g_yh[(size_t)MM * CC];
__device__ __half g_yl[(size_t)MM * CC];

// ---------------------------------------------------------------------------
// Helpers (sm_103 base-target: ldmatrix / mma.sync / cp.async)
// ---------------------------------------------------------------------------
__device__ __forceinline__ uint32_t smem_to_u32(const void* p) {
    uint32_t a;
    asm("{ .reg .u64 t; cvta.to.shared.u64 t, %1; cvt.u32.u64 %0, t; }"
        : "=r"(a) : "l"(p));
    return a;
}

#define SWZ(off) ((off) ^ (((off) >> 3) & 0x70))

__device__ __forceinline__ void cp16(uint32_t saddr, const void* g) {
    asm volatile("cp.async.cg.shared.global [%0], [%1], 16;"
                 :: "r"(saddr), "l"(g));
}
#define CP_COMMIT() asm volatile("cp.async.commit_group;" ::: "memory")
#define CP_WAIT(n)  asm volatile("cp.async.wait_group %0;" :: "n"(n) : "memory")

#define LDSM4(r, addr) \
    asm volatile("ldmatrix.sync.aligned.m8n8.x4.shared.b16 {%0,%1,%2,%3}, [%4];" \
        : "=r"((r)[0]), "=r"((r)[1]), "=r"((r)[2]), "=r"((r)[3]) : "r"(addr))

#define LDSM4T(r, addr) \
    asm volatile("ldmatrix.sync.aligned.m8n8.x4.trans.shared.b16 {%0,%1,%2,%3}, [%4];" \
        : "=r"((r)[0]), "=r"((r)[1]), "=r"((r)[2]), "=r"((r)[3]) : "r"(addr))

// fp16 MMA, fp32 accumulate
#define MMA16816(d, a, b0v, b1v) \
    asm volatile("mma.sync.aligned.m16n8k16.row.col.f32.f16.f16.f32 " \
        "{%0,%1,%2,%3}, {%4,%5,%6,%7}, {%8,%9}, {%0,%1,%2,%3};" \
        : "+f"((d)[0]), "+f"((d)[1]), "+f"((d)[2]), "+f"((d)[3]) \
        : "r"((a)[0]), "r"((a)[1]), "r"((a)[2]), "r"((a)[3]), "r"(b0v), "r"(b1v))

__device__ __forceinline__ uint32_t pack_h2(float a, float b) {
    __half2 t = __floats2half2_rn(a, b);
    return *(uint32_t*)&t;
}

// ---------------------------------------------------------------------------
// fp32 -> fp16 hi(+lo) planes
// ---------------------------------------------------------------------------
template <bool LO>
__global__ void __launch_bounds__(256) split_f16(const float* __restrict__ in,
                                                 __half* __restrict__ hi,
                                                 __half* __restrict__ lo,
                                                 int n4) {
    int i = blockIdx.x * 256 + threadIdx.x;
    if (i >= n4) return;
    float4 v = ((const float4*)in)[i];
    __half h0 = __float2half_rn(v.x);
    __half h1 = __float2half_rn(v.y);
    __half h2 = __float2half_rn(v.z);
    __half h3 = __float2half_rn(v.w);
    ((__half2*)hi)[i * 2 + 0] = __half2(h0, h1);
    ((__half2*)hi)[i * 2 + 1] = __half2(h2, h3);
    if (LO) {
        __half l0 = __float2half_rn(v.x - __half2float(h0));
        __half l1 = __float2half_rn(v.y - __half2float(h1));
        __half l2 = __float2half_rn(v.z - __half2float(h2));
        __half l3 = __float2half_rn(v.w - __half2float(h3));
        ((__half2*)lo)[i * 2 + 0] = __half2(l0, l1);
        ((__half2*)lo)[i * 2 + 1] = __half2(l2, l3);
    }
}

// ---------------------------------------------------------------------------
// HMMA GEMM: C[M,N] = A[M,K] @ B[N,K]^T, A = Ah+Al (fp16 split), B = Bh (fp16).
// 2-term: C = Ah*Bh + Al*Bh. Tile 128x128, K-chunk 64, 128 thr (4 warps 2x2),
// warp tile 64x64. 2-stage cp.async @ 96KB smem -> 2 CTAs/SM.
// SPLIT=true: write fp16 hi plane (+lo plane for q cols bn<1024, q scaled 1/8).
// ---------------------------------------------------------------------------
#define NSTAGE 2
#define STAGE_BYTES 49152          // AH 16K | AL 16K | BH 16K
#define GEMM_SMEM (NSTAGE * STAGE_BYTES)   // 98304

template <bool SPLIT>
__global__ void __launch_bounds__(128, 2) gemm_hmma2(
    const __half* __restrict__ Ah, const __half* __restrict__ Al,
    const __half* __restrict__ Bh,
    float* __restrict__ C, __half* __restrict__ Ch, __half* __restrict__ Cl,
    int M, int N, int K) {
    extern __shared__ char smem[];
    const uint32_t sbase = smem_to_u32(smem);
    const int tid = threadIdx.x;
    const int lane = tid & 31;
    const int wid = tid >> 5;      // 0..3
    const int wm = wid >> 1;       // 0..1
    const int wn = wid & 1;        // 0..1
    const int bm = blockIdx.y * 128;
    const int bn = blockIdx.x * 128;

    float acc[4][8][4];
#pragma unroll
    for (int i = 0; i < 4; i++)
#pragma unroll
        for (int j = 0; j < 8; j++)
#pragma unroll
            for (int t = 0; t < 4; t++) acc[i][j][t] = 0.f;

    const int nch = K >> 6;        // K-chunk 64
    const int uL = tid & 7;        // 16B unit within 128B row
    const int rowL = tid >> 3;     // 0..15

    auto ld_chunk = [&](int c, int st) {
        const int k0 = c << 6;
        const uint32_t sS = sbase + st * STAGE_BYTES;
        const __half* gAh = Ah + (size_t)bm * K + k0 + uL * 8;
        const __half* gAl = Al + (size_t)bm * K + k0 + uL * 8;
        const __half* gB  = Bh + (size_t)bn * K + k0 + uL * 8;
#pragma unroll
        for (int it = 0; it < 8; it++) {
            int row = rowL + it * 16;
            uint32_t so = SWZ(row * 128 + uL * 16);
            cp16(sS + so,          gAh + (size_t)row * K);
            cp16(sS + 16384 + so,  gAl + (size_t)row * K);
            cp16(sS + 32768 + so,  gB  + (size_t)row * K);
        }
    };

    auto compute = [&](int st) {
        const uint32_t sAH = sbase + st * STAGE_BYTES;
        const uint32_t sAL = sAH + 16384;
        const uint32_t sBH = sAH + 32768;
#pragma unroll
        for (int ks = 0; ks < 4; ks++) {
            uint32_t ah[4][4], al[4][4];
            const int rA = lane & 15;
            const int uA = ks * 2 + (lane >> 4);
#pragma unroll
            for (int mi = 0; mi < 4; mi++) {
                int mrow = wm * 64 + mi * 16 + rA;
                uint32_t so = SWZ(mrow * 128 + uA * 16);
                LDSM4(ah[mi], sAH + so);
                LDSM4(al[mi], sAL + so);
            }
            const int rB = (lane & 7) + ((lane & 16) >> 1);
            const int uB = ks * 2 + ((lane & 8) >> 3);
#pragma unroll
            for (int nb = 0; nb < 4; nb++) {
                int nrow = wn * 64 + nb * 16 + rB;
                uint32_t bh[4];
                LDSM4(bh, sBH + SWZ(nrow * 128 + uB * 16));
#pragma unroll
                for (int mi = 0; mi < 4; mi++) {
                    MMA16816(acc[mi][nb * 2 + 0], ah[mi], bh[0], bh[1]);
                    MMA16816(acc[mi][nb * 2 + 1], ah[mi], bh[2], bh[3]);
                    MMA16816(acc[mi][nb * 2 + 0], al[mi], bh[0], bh[1]);
                    MMA16816(acc[mi][nb * 2 + 1], al[mi], bh[2], bh[3]);
                }
            }
        }
    };

    ld_chunk(0, 0); CP_COMMIT();
    if (nch > 1) { ld_chunk(1, 1); CP_COMMIT(); }

    for (int c = 0; c < nch; c++) {
        if (c + 1 < nch) CP_WAIT(1);
        else             CP_WAIT(0);
        __syncthreads();
        compute(c & 1);
        __syncthreads();
        if (c + 2 < nch) {
            ld_chunk(c + 2, c & 1);
            CP_COMMIT();
        }
    }

    // Epilogue
    const int er = lane >> 2;
    const int ec = (lane & 3) * 2;
    const bool qreg = (bn < 1024);
    const float sc = (SPLIT && qreg) ? 0.125f : 1.0f;   // fold q scale
#pragma unroll
    for (int mi = 0; mi < 4; mi++) {
#pragma unroll
        for (int nj = 0; nj < 8; nj++) {
            int row = bm + wm * 64 + mi * 16 + er;
            int col = bn + wn * 64 + nj * 8 + ec;
            if (SPLIT) {
#pragma unroll
                for (int rr = 0; rr < 2; rr++) {
                    float a0 = acc[mi][nj][rr * 2 + 0] * sc;
                    float a1 = acc[mi][nj][rr * 2 + 1] * sc;
                    __half h0 = __float2half_rn(a0);
                    __half h1 = __float2half_rn(a1);
                    size_t off = (size_t)(row + rr * 8) * N + col;
                    *(__half2*)(Ch + off) = __half2(h0, h1);
                    if (qreg) {   // lo plane needed only for q
                        __half l0 = __float2half_rn(a0 - __half2float(h0));
                        __half l1 = __float2half_rn(a1 - __half2float(h1));
                        *(__half2*)(Cl + off) = __half2(l0, l1);
                    }
                }
            } else {
                float2 v0 = make_float2(acc[mi][nj][0], acc[mi][nj][1]);
                float2 v1 = make_float2(acc[mi][nj][2], acc[mi][nj][3]);
                *(float2*)(C + (size_t)row * N + col) = v0;
                *(float2*)(C + (size_t)(row + 8) * N + col) = v1;
            }
        }
    }
}

// ---------------------------------------------------------------------------
// HMMA flash attention (causal), fp16 2-term. CTA = 128 q rows, 4 warps
// (32 rows each). Q split hi/lo (persistent frags), K/V hi-plane only.
// S = Qh*Kh + Ql*Kh; O += Ph*Vh + Pl*Vh (P split in-register).
// K/V chunks of 64 keys, 2-stage cp.async (16KB/stage). 128 threads.
// ---------------------------------------------------------------------------
#define AQH 0
#define AQL 16384
#define AST(s) (32768 + (s) * 16384)   // stage: KH +0 (8K), VH +8192 (8K)
#define ATTN_SMEM (32768 + 2 * 16384)  // 65536

__global__ void __launch_bounds__(128) attn_hmma(
    const __half* __restrict__ qkvh, const __half* __restrict__ qkvl,
    __half* __restrict__ yh, __half* __restrict__ yl) {
    extern __shared__ char smem[];
    const uint32_t sb = smem_to_u32(smem);
    const int qt = blockIdx.x;
    const int h  = blockIdx.y;
    const int b  = blockIdx.z;
    const int tid = threadIdx.x;
    const int lane = tid & 31;
    const int wid = tid >> 5;      // 0..3, each warp owns 32 q rows

    const size_t tok0 = (size_t)b * TT;

    // ---- Q tile load (128 rows x 64 d, hi+lo) ----
    {
        const int u = tid & 7;
        const int r = tid >> 3;    // 0..15
#pragma unroll
        for (int p = 0; p < 2; p++) {
            const __half* gq =
                (p ? qkvl : qkvh) + (tok0 + (size_t)qt * 128) * C3 + h * DD + u * 8;
            const uint32_t sq = sb + (p ? AQL : AQH);
#pragma unroll
            for (int it = 0; it < 8; it++) {
                int row = r + it * 16;
                cp16(sq + SWZ(row * 128 + u * 16), gq + (size_t)row * C3);
            }
        }
    }

    auto ld_kv = [&](int kc, int st) {
        const int u = tid & 7;
        const int r = tid >> 3;    // 0..15
        const uint32_t sst = sb + AST(st);
        const size_t trow = tok0 + (size_t)kc * 64;
        const __half* gK = qkvh + trow * C3 + CC + h * DD + u * 8;
        const __half* gV = qkvh + trow * C3 + 2 * CC + h * DD + u * 8;
#pragma unroll
        for (int it = 0; it < 4; it++) {
            int row = r + it * 16;
            uint32_t so = SWZ(row * 128 + u * 16);
            cp16(sst + so,        gK + (size_t)row * C3);
            cp16(sst + 8192 + so, gV + (size_t)row * C3);
        }
    };

    const int nch = 2 * qt + 2;
    ld_kv(0, 0);
    CP_COMMIT();
    if (nch > 1) { ld_kv(1, 1); CP_COMMIT(); }

    uint32_t qh[2][4][4], ql[2][4][4];
    float o[2][8][4];
#pragma unroll
    for (int mi = 0; mi < 2; mi++)
#pragma unroll
        for (int j = 0; j < 8; j++)
#pragma unroll
            for (int t = 0; t < 4; t++) o[mi][j][t] = 0.f;
    float mm0[2] = {-1e30f, -1e30f}, mm1[2] = {-1e30f, -1e30f};
    float ll0[2] = {0.f, 0.f},       ll1[2] = {0.f, 0.f};

    const int qrow_lo = qt * 128 + wid * 32;          // warp's first q row
    const int r0 = lane >> 2;
    const int c0 = (lane & 3) * 2;

    for (int kc = 0; kc < nch; kc++) {
        if (kc + 1 < nch) CP_WAIT(1); else CP_WAIT(0);
        __syncthreads();

        if (kc == 0) {
            // Q fragments (persistent): 2 mi blocks of 16 rows
#pragma unroll
            for (int mi = 0; mi < 2; mi++) {
#pragma unroll
                for (int ks = 0; ks < 4; ks++) {
                    const int rA = lane & 15;
                    const int uA = ks * 2 + (lane >> 4);
                    uint32_t a = SWZ((wid * 32 + mi * 16 + rA) * 128 + uA * 16);
                    LDSM4(qh[mi][ks], sb + AQH + a);
                    LDSM4(ql[mi][ks], sb + AQL + a);
                }
            }
        }

        if (kc * 64 <= qrow_lo + 31) {
            const uint32_t sK = sb + AST(kc & 1);
            const uint32_t sV = sK + 8192;

            // ---- S = Q @ K^T (2-term) ----
            float s[2][8][4];
#pragma unroll
            for (int mi = 0; mi < 2; mi++)
#pragma unroll
                for (int j = 0; j < 8; j++)
#pragma unroll
                    for (int t = 0; t < 4; t++) s[mi][j][t] = 0.f;

            const int rB = (lane & 7) + ((lane & 16) >> 1);
#pragma unroll
            for (int ks = 0; ks < 4; ks++) {
                const int uB = ks * 2 + ((lane & 8) >> 3);
#pragma unroll
                for (int nb = 0; nb < 4; nb++) {
                    uint32_t kh4[4];
                    LDSM4(kh4, sK + SWZ((nb * 16 + rB) * 128 + uB * 16));
#pragma unroll
                    for (int mi = 0; mi < 2; mi++) {
                        MMA16816(s[mi][nb * 2 + 0], qh[mi][ks], kh4[0], kh4[1]);
                        MMA16816(s[mi][nb * 2 + 1], qh[mi][ks], kh4[2], kh4[3]);
                        MMA16816(s[mi][nb * 2 + 0], ql[mi][ks], kh4[0], kh4[1]);
                        MMA16816(s[mi][nb * 2 + 1], ql[mi][ks], kh4[2], kh4[3]);
                    }
                }
            }

            // ---- causal mask (near diagonal only) ----
            if (kc * 64 + 63 > qrow_lo) {
#pragma unroll
                for (int mi = 0; mi < 2; mi++) {
                    const int qr0 = qrow_lo + mi * 16 + r0;
#pragma unroll
                    for (int j = 0; j < 8; j++) {
                        int kcol = kc * 64 + 8 * j + c0;
                        if (kcol > qr0)         s[mi][j][0] = -1e30f;
                        if (kcol + 1 > qr0)     s[mi][j][1] = -1e30f;
                        if (kcol > qr0 + 8)     s[mi][j][2] = -1e30f;
                        if (kcol + 1 > qr0 + 8) s[mi][j][3] = -1e30f;
                    }
                }
            }

            // ---- online softmax + pack P (fp16 hi/lo), per mi ----
            uint32_t ph[2][4][4], pl[2][4][4];
#pragma unroll
            for (int mi = 0; mi < 2; mi++) {
                float mx0 = -1e30f, mx1 = -1e30f;
#pragma unroll
                for (int j = 0; j < 8; j++) {
                    mx0 = fmaxf(mx0, fmaxf(s[mi][j][0], s[mi][j][1]));
                    mx1 = fmaxf(mx1, fmaxf(s[mi][j][2], s[mi][j][3]));
                }
                mx0 = fmaxf(mx0, __shfl_xor_sync(0xffffffffu, mx0, 1));
                mx0 = fmaxf(mx0, __shfl_xor_sync(0xffffffffu, mx0, 2));
                mx1 = fmaxf(mx1, __shfl_xor_sync(0xffffffffu, mx1, 1));
                mx1 = fmaxf(mx1, __shfl_xor_sync(0xffffffffu, mx1, 2));
                float mn0 = fmaxf(mm0[mi], mx0);
                float mn1 = fmaxf(mm1[mi], mx1);
                float corr0 = __expf(mm0[mi] - mn0);
                float corr1 = __expf(mm1[mi] - mn1);
                float ls0 = 0.f, ls1 = 0.f;
#pragma unroll
                for (int j = 0; j < 8; j++) {
                    s[mi][j][0] = __expf(s[mi][j][0] - mn0);
                    s[mi][j][1] = __expf(s[mi][j][1] - mn0);
                    s[mi][j][2] = __expf(s[mi][j][2] - mn1);
                    s[mi][j][3] = __expf(s[mi][j][3] - mn1);
                    ls0 += s[mi][j][0] + s[mi][j][1];
                    ls1 += s[mi][j][2] + s[mi][j][3];
                }
                ls0 += __shfl_xor_sync(0xffffffffu, ls0, 1);
                ls0 += __shfl_xor_sync(0xffffffffu, ls0, 2);
                ls1 += __shfl_xor_sync(0xffffffffu, ls1, 1);
                ls1 += __shfl_xor_sync(0xffffffffu, ls1, 2);
                ll0[mi] = ll0[mi] * corr0 + ls0;
                ll1[mi] = ll1[mi] * corr1 + ls1;
                mm0[mi] = mn0; mm1[mi] = mn1;
#pragma unroll
                for (int j = 0; j < 8; j++) {
                    o[mi][j][0] *= corr0; o[mi][j][1] *= corr0;
                    o[mi][j][2] *= corr1; o[mi][j][3] *= corr1;
                }
#pragma unroll
                for (int ks = 0; ks < 4; ks++) {
                    const int j0 = 2 * ks, j1 = 2 * ks + 1;
                    float v0 = s[mi][j0][0], v1 = s[mi][j0][1];
                    float v2 = s[mi][j0][2], v3 = s[mi][j0][3];
                    float w0 = s[mi][j1][0], w1 = s[mi][j1][1];
                    float w2 = s[mi][j1][2], w3 = s[mi][j1][3];
                    ph[mi][ks][0] = pack_h2(v0, v1);
                    ph[mi][ks][1] = pack_h2(v2, v3);
                    ph[mi][ks][2] = pack_h2(w0, w1);
                    ph[mi][ks][3] = pack_h2(w2, w3);
                    __half2 hh;
                    hh = *(__half2*)&ph[mi][ks][0];
                    pl[mi][ks][0] = pack_h2(v0 - __half2float(hh.x),
                                            v1 - __half2float(hh.y));
                    hh = *(__half2*)&ph[mi][ks][1];
                    pl[mi][ks][1] = pack_h2(v2 - __half2float(hh.x),
                                            v3 - __half2float(hh.y));
                    hh = *(__half2*)&ph[mi][ks][2];
                    pl[mi][ks][2] = pack_h2(w0 - __half2float(hh.x),
                                            w1 - __half2float(hh.y));
                    hh = *(__half2*)&ph[mi][ks][3];
                    pl[mi][ks][3] = pack_h2(w2 - __half2float(hh.x),
                                            w3 - __half2float(hh.y));
                }
            }

            // ---- O += P @ V (V^T fragments via ldmatrix.trans, 2-term) ----
#pragma unroll
            for (int ks = 0; ks < 4; ks++) {
#pragma unroll
                for (int db = 0; db < 4; db++) {
                    uint32_t vh4[4];
                    uint32_t a = SWZ((ks * 16 + (lane & 7) + ((lane >> 3) & 1) * 8) * 128 +
                                     ((lane >> 4) + db * 2) * 16);
                    LDSM4T(vh4, sV + a);
#pragma unroll
                    for (int mi = 0; mi < 2; mi++) {
                        MMA16816(o[mi][db * 2 + 0], ph[mi][ks], vh4[0], vh4[1]);
                        MMA16816(o[mi][db * 2 + 1], ph[mi][ks], vh4[2], vh4[3]);
                        MMA16816(o[mi][db * 2 + 0], pl[mi][ks], vh4[0], vh4[1]);
                        MMA16816(o[mi][db * 2 + 1], pl[mi][ks], vh4[2], vh4[3]);
                    }
                }
            }
        }

        __syncthreads();
        if (kc + 2 < nch) {
            ld_kv(kc + 2, kc & 1);
            CP_COMMIT();
        }
    }

    // ---- epilogue: normalize, split hi/lo (fp16), write yh/yl ----
#pragma unroll
    for (int mi = 0; mi < 2; mi++) {
        const float i0 = 1.f / ll0[mi];
        const float i1 = 1.f / ll1[mi];
        const size_t tokA = tok0 + (size_t)qt * 128 + wid * 32 + mi * 16 + r0;
#pragma unroll
        for (int j = 0; j < 8; j++) {
            int dc = h * DD + 8 * j + c0;
            float a0 = o[mi][j][0] * i0, a1 = o[mi][j][1] * i0;
            float b0 = o[mi][j][2] * i1, b1 = o[mi][j][3] * i1;
            __half h0 = __float2half_rn(a0), h1 = __float2half_rn(a1);
            __half h2 = __float2half_rn(b0), h3 = __float2half_rn(b1);
            size_t offA = tokA * CC + dc;
            size_t offB = (tokA + 8) * CC + dc;
            *(__half2*)(yh + offA) = __half2(h0, h1);
            *(__half2*)(yh + offB) = __half2(h2, h3);
            *(__half2*)(yl + offA) = __half2(
                __float2half_rn(a0 - __half2float(h0)),
                __float2half_rn(a1 - __half2float(h1)));
            *(__half2*)(yl + offB) = __half2(
                __float2half_rn(b0 - __half2float(h2)),
                __float2half_rn(b1 - __half2float(h3)));
        }
    }
}

// ---------------------------------------------------------------------------
extern "C" void kernel_launch(void* const* d_in, const int* in_sizes, int n_in,
                              void* d_out, int out_size) {
    const float* x      = (const float*)d_in[0];
    const float* w_attn = (const float*)d_in[1];
    const float* w_proj = (const float*)d_in[2];
    float* out = (float*)d_out;

    void *xh_p, *xl_p, *wah_p, *wph_p, *qh_p, *ql_p, *yh_p, *yl_p;
    cudaGetSymbolAddress(&xh_p, g_xh);
    cudaGetSymbolAddress(&xl_p, g_xl);
    cudaGetSymbolAddress(&wah_p, g_wah);
    cudaGetSymbolAddress(&wph_p, g_wph);
    cudaGetSymbolAddress(&qh_p, g_qkvh);
    cudaGetSymbolAddress(&ql_p, g_qkvl);
    cudaGetSymbolAddress(&yh_p, g_yh);
    cudaGetSymbolAddress(&yl_p, g_yl);

    cudaFuncSetAttribute(gemm_hmma2<true>,
                         cudaFuncAttributeMaxDynamicSharedMemorySize, GEMM_SMEM);
    cudaFuncSetAttribute(gemm_hmma2<false>,
                         cudaFuncAttributeMaxDynamicSharedMemorySize, GEMM_SMEM);
    cudaFuncSetAttribute(attn_hmma,
                         cudaFuncAttributeMaxDynamicSharedMemorySize, ATTN_SMEM);

    // 1) x -> fp16 hi/lo; weights -> fp16 hi only
    split_f16<true><<<(MM * CC / 4 + 255) / 256, 256>>>(
        x, (__half*)xh_p, (__half*)xl_p, MM * CC / 4);
    split_f16<false><<<(C3 * CC / 4 + 255) / 256, 256>>>(
        w_attn, (__half*)wah_p, nullptr, C3 * CC / 4);
    split_f16<false><<<(CC * CC / 4 + 255) / 256, 256>>>(
        w_proj, (__half*)wph_p, nullptr, CC * CC / 4);

    // 2) QKV gemm -> fp16 hi plane (+lo for q cols; q pre-scaled by 1/8)
    gemm_hmma2<true><<<dim3(C3 / 128, MM / 128), 128, GEMM_SMEM>>>(
        (const __half*)xh_p, (const __half*)xl_p, (const __half*)wah_p,
        nullptr, (__half*)qh_p, (__half*)ql_p, MM, C3, CC);

    // 3) HMMA flash attention -> yh/yl
    attn_hmma<<<dim3(TT / 128, HH, BB), 128, ATTN_SMEM>>>(
        (const __half*)qh_p, (const __half*)ql_p,
        (__half*)yh_p, (__half*)yl_p);

    // 4) out = y @ w_proj^T (fp32 out)
    gemm_hmma2<false><<<dim3(CC / 128, MM / 128), 128, GEMM_SMEM>>>(
        (const __half*)yh_p, (const __half*)yl_p, (const __half*)wph_p,
        out, nullptr, nullptr, MM, CC, CC);
}

// round 11
// speedup vs baseline: 1.8352x; 1.0947x over previous
#include <cuda_runtime.h>
#include <cuda_fp16.h>
#include <cstdint>
#include <math.h>

// Problem dims
#define BB 2
#define TT 2048
#define CC 1024
#define HH 16
#define DD 64
#define C3 3072
#define MM (BB * TT)   // 4096

// ---------------------------------------------------------------------------
// Scratch (device globals; no allocation allowed)
// ---------------------------------------------------------------------------
__device__ __half g_xh[(size_t)MM * CC];
__device__ __half g_xl[(size_t)MM * CC];
__device__ __half g_wah[(size_t)C3 * CC];
__device__ __half g_wph[(size_t)CC * CC];
__device__ __half g_qkvh[(size_t)MM * C3];
__device__ __half g_qkvl[(size_t)MM * C3];   // lo only used/written for q cols
__device__ __half g_yh[(size_t)MM * CC];
__device__ __half g_yl[(size_t)MM * CC];

// ---------------------------------------------------------------------------
// Helpers (sm_103 base-target: ldmatrix / mma.sync / cp.async)
// ---------------------------------------------------------------------------
__device__ __forceinline__ uint32_t smem_to_u32(const void* p) {
    uint32_t a;
    asm("{ .reg .u64 t; cvta.to.shared.u64 t, %1; cvt.u32.u64 %0, t; }"
        : "=r"(a) : "l"(p));
    return a;
}

#define SWZ(off) ((off) ^ (((off) >> 3) & 0x70))

__device__ __forceinline__ void cp16(uint32_t saddr, const void* g) {
    asm volatile("cp.async.cg.shared.global [%0], [%1], 16;"
                 :: "r"(saddr), "l"(g));
}
#define CP_COMMIT() asm volatile("cp.async.commit_group;" ::: "memory")
#define CP_WAIT(n)  asm volatile("cp.async.wait_group %0;" :: "n"(n) : "memory")

#define LDSM4(r, addr) \
    asm volatile("ldmatrix.sync.aligned.m8n8.x4.shared.b16 {%0,%1,%2,%3}, [%4];" \
        : "=r"((r)[0]), "=r"((r)[1]), "=r"((r)[2]), "=r"((r)[3]) : "r"(addr))

#define LDSM4T(r, addr) \
    asm volatile("ldmatrix.sync.aligned.m8n8.x4.trans.shared.b16 {%0,%1,%2,%3}, [%4];" \
        : "=r"((r)[0]), "=r"((r)[1]), "=r"((r)[2]), "=r"((r)[3]) : "r"(addr))

// fp16 MMA, fp32 accumulate
#define MMA16816(d, a, b0v, b1v) \
    asm volatile("mma.sync.aligned.m16n8k16.row.col.f32.f16.f16.f32 " \
        "{%0,%1,%2,%3}, {%4,%5,%6,%7}, {%8,%9}, {%0,%1,%2,%3};" \
        : "+f"((d)[0]), "+f"((d)[1]), "+f"((d)[2]), "+f"((d)[3]) \
        : "r"((a)[0]), "r"((a)[1]), "r"((a)[2]), "r"((a)[3]), "r"(b0v), "r"(b1v))

__device__ __forceinline__ uint32_t pack_h2(float a, float b) {
    __half2 t = __floats2half2_rn(a, b);
    return *(uint32_t*)&t;
}

// ---------------------------------------------------------------------------
// fp32 -> fp16 hi(+lo) planes
// ---------------------------------------------------------------------------
template <bool LO>
__global__ void __launch_bounds__(256) split_f16(const float* __restrict__ in,
                                                 __half* __restrict__ hi,
                                                 __half* __restrict__ lo,
                                                 int n4) {
    int i = blockIdx.x * 256 + threadIdx.x;
    if (i >= n4) return;
    float4 v = ((const float4*)in)[i];
    __half h0 = __float2half_rn(v.x);
    __half h1 = __float2half_rn(v.y);
    __half h2 = __float2half_rn(v.z);
    __half h3 = __float2half_rn(v.w);
    ((__half2*)hi)[i * 2 + 0] = __half2(h0, h1);
    ((__half2*)hi)[i * 2 + 1] = __half2(h2, h3);
    if (LO) {
        __half l0 = __float2half_rn(v.x - __half2float(h0));
        __half l1 = __float2half_rn(v.y - __half2float(h1));
        __half l2 = __float2half_rn(v.z - __half2float(h2));
        __half l3 = __float2half_rn(v.w - __half2float(h3));
        ((__half2*)lo)[i * 2 + 0] = __half2(l0, l1);
        ((__half2*)lo)[i * 2 + 1] = __half2(l2, l3);
    }
}

// ---------------------------------------------------------------------------
// HMMA GEMM: C[M,N] = A[M,K] @ B[N,K]^T, A = Ah+Al (fp16 split), B = Bh (fp16).
// Tile 128x128, K-chunk 64, 128 thr (4 warps 2x2), warp tile 64x64.
// 2-stage cp.async @ 96KB smem -> 2 CTAs/SM.
// SPLIT=true (QKV): Q cols (bn<1024) use 2-term C=Ah*Bh+Al*Bh and write hi+lo;
//                   K/V cols use 1-term C=Ah*Bh (error ~= fp16 storage rounding)
//                   and write hi only. Q is pre-scaled by 1/8.
// SPLIT=false (proj): always 2-term, fp32 output.
// ---------------------------------------------------------------------------
#define NSTAGE 2
#define STAGE_BYTES 49152          // AH 16K | AL 16K | BH 16K
#define GEMM_SMEM (NSTAGE * STAGE_BYTES)   // 98304

template <bool SPLIT>
__global__ void __launch_bounds__(128, 2) gemm_hmma2(
    const __half* __restrict__ Ah, const __half* __restrict__ Al,
    const __half* __restrict__ Bh,
    float* __restrict__ C, __half* __restrict__ Ch, __half* __restrict__ Cl,
    int M, int N, int K) {
    extern __shared__ char smem[];
    const uint32_t sbase = smem_to_u32(smem);
    const int tid = threadIdx.x;
    const int lane = tid & 31;
    const int wid = tid >> 5;      // 0..3
    const int wm = wid >> 1;       // 0..1
    const int wn = wid & 1;        // 0..1
    const int bm = blockIdx.y * 128;
    const int bn = blockIdx.x * 128;

    const bool twoterm = !SPLIT || (bn < 1024);   // Q cols need the Al term

    float acc[4][8][4];
#pragma unroll
    for (int i = 0; i < 4; i++)
#pragma unroll
        for (int j = 0; j < 8; j++)
#pragma unroll
            for (int t = 0; t < 4; t++) acc[i][j][t] = 0.f;

    const int nch = K >> 6;        // K-chunk 64
    const int uL = tid & 7;        // 16B unit within 128B row
    const int rowL = tid >> 3;     // 0..15

    auto ld_chunk = [&](int c, int st) {
        const int k0 = c << 6;
        const uint32_t sS = sbase + st * STAGE_BYTES;
        const __half* gAh = Ah + (size_t)bm * K + k0 + uL * 8;
        const __half* gAl = Al + (size_t)bm * K + k0 + uL * 8;
        const __half* gB  = Bh + (size_t)bn * K + k0 + uL * 8;
#pragma unroll
        for (int it = 0; it < 8; it++) {
            int row = rowL + it * 16;
            uint32_t so = SWZ(row * 128 + uL * 16);
            cp16(sS + so,         gAh + (size_t)row * K);
            if (twoterm) cp16(sS + 16384 + so, gAl + (size_t)row * K);
            cp16(sS + 32768 + so, gB + (size_t)row * K);
        }
    };

    // 2-term compute: Ah*Bh + Al*Bh
    auto compute2 = [&](int st) {
        const uint32_t sAH = sbase + st * STAGE_BYTES;
        const uint32_t sAL = sAH + 16384;
        const uint32_t sBH = sAH + 32768;
#pragma unroll
        for (int ks = 0; ks < 4; ks++) {
            uint32_t ah[4][4], al[4][4];
            const int rA = lane & 15;
            const int uA = ks * 2 + (lane >> 4);
#pragma unroll
            for (int mi = 0; mi < 4; mi++) {
                int mrow = wm * 64 + mi * 16 + rA;
                uint32_t so = SWZ(mrow * 128 + uA * 16);
                LDSM4(ah[mi], sAH + so);
                LDSM4(al[mi], sAL + so);
            }
            const int rB = (lane & 7) + ((lane & 16) >> 1);
            const int uB = ks * 2 + ((lane & 8) >> 3);
#pragma unroll
            for (int nb = 0; nb < 4; nb++) {
                int nrow = wn * 64 + nb * 16 + rB;
                uint32_t bh[4];
                LDSM4(bh, sBH + SWZ(nrow * 128 + uB * 16));
#pragma unroll
                for (int mi = 0; mi < 4; mi++) {
                    MMA16816(acc[mi][nb * 2 + 0], ah[mi], bh[0], bh[1]);
                    MMA16816(acc[mi][nb * 2 + 1], ah[mi], bh[2], bh[3]);
                    MMA16816(acc[mi][nb * 2 + 0], al[mi], bh[0], bh[1]);
                    MMA16816(acc[mi][nb * 2 + 1], al[mi], bh[2], bh[3]);
                }
            }
        }
    };

    // 1-term compute: Ah*Bh only (K/V output columns)
    auto compute1 = [&](int st) {
        const uint32_t sAH = sbase + st * STAGE_BYTES;
        const uint32_t sBH = sAH + 32768;
#pragma unroll
        for (int ks = 0; ks < 4; ks++) {
            uint32_t ah[4][4];
            const int rA = lane & 15;
            const int uA = ks * 2 + (lane >> 4);
#pragma unroll
            for (int mi = 0; mi < 4; mi++) {
                int mrow = wm * 64 + mi * 16 + rA;
                LDSM4(ah[mi], sAH + SWZ(mrow * 128 + uA * 16));
            }
            const int rB = (lane & 7) + ((lane & 16) >> 1);
            const int uB = ks * 2 + ((lane & 8) >> 3);
#pragma unroll
            for (int nb = 0; nb < 4; nb++) {
                int nrow = wn * 64 + nb * 16 + rB;
                uint32_t bh[4];
                LDSM4(bh, sBH + SWZ(nrow * 128 + uB * 16));
#pragma unroll
                for (int mi = 0; mi < 4; mi++) {
                    MMA16816(acc[mi][nb * 2 + 0], ah[mi], bh[0], bh[1]);
                    MMA16816(acc[mi][nb * 2 + 1], ah[mi], bh[2], bh[3]);
                }
            }
        }
    };

    ld_chunk(0, 0); CP_COMMIT();
    if (nch > 1) { ld_chunk(1, 1); CP_COMMIT(); }

    for (int c = 0; c < nch; c++) {
        if (c + 1 < nch) CP_WAIT(1);
        else             CP_WAIT(0);
        __syncthreads();
        if (twoterm) compute2(c & 1);
        else         compute1(c & 1);
        __syncthreads();
        if (c + 2 < nch) {
            ld_chunk(c + 2, c & 1);
            CP_COMMIT();
        }
    }

    // Epilogue
    const int er = lane >> 2;
    const int ec = (lane & 3) * 2;
    const bool qreg = (bn < 1024);
    const float sc = (SPLIT && qreg) ? 0.125f : 1.0f;   // fold q scale
#pragma unroll
    for (int mi = 0; mi < 4; mi++) {
#pragma unroll
        for (int nj = 0; nj < 8; nj++) {
            int row = bm + wm * 64 + mi * 16 + er;
            int col = bn + wn * 64 + nj * 8 + ec;
            if (SPLIT) {
#pragma unroll
                for (int rr = 0; rr < 2; rr++) {
                    float a0 = acc[mi][nj][rr * 2 + 0] * sc;
                    float a1 = acc[mi][nj][rr * 2 + 1] * sc;
                    __half h0 = __float2half_rn(a0);
                    __half h1 = __float2half_rn(a1);
                    size_t off = (size_t)(row + rr * 8) * N + col;
                    *(__half2*)(Ch + off) = __half2(h0, h1);
                    if (qreg) {   // lo plane needed only for q
                        __half l0 = __float2half_rn(a0 - __half2float(h0));
                        __half l1 = __float2half_rn(a1 - __half2float(h1));
                        *(__half2*)(Cl + off) = __half2(l0, l1);
                    }
                }
            } else {
                float2 v0 = make_float2(acc[mi][nj][0], acc[mi][nj][1]);
                float2 v1 = make_float2(acc[mi][nj][2], acc[mi][nj][3]);
                *(float2*)(C + (size_t)row * N + col) = v0;
                *(float2*)(C + (size_t)(row + 8) * N + col) = v1;
            }
        }
    }
}

// ---------------------------------------------------------------------------
// HMMA flash attention (causal), fp16 2-term — unchanged from round 10.
// CTA = 128 q rows, 4 warps (32 rows each). Q split hi/lo, K/V hi-plane only.
// ---------------------------------------------------------------------------
#define AQH 0
#define AQL 16384
#define AST(s) (32768 + (s) * 16384)   // stage: KH +0 (8K), VH +8192 (8K)
#define ATTN_SMEM (32768 + 2 * 16384)  // 65536

__global__ void __launch_bounds__(128) attn_hmma(
    const __half* __restrict__ qkvh, const __half* __restrict__ qkvl,
    __half* __restrict__ yh, __half* __restrict__ yl) {
    extern __shared__ char smem[];
    const uint32_t sb = smem_to_u32(smem);
    const int qt = blockIdx.x;
    const int h  = blockIdx.y;
    const int b  = blockIdx.z;
    const int tid = threadIdx.x;
    const int lane = tid & 31;
    const int wid = tid >> 5;      // 0..3, each warp owns 32 q rows

    const size_t tok0 = (size_t)b * TT;

    // ---- Q tile load (128 rows x 64 d, hi+lo) ----
    {
        const int u = tid & 7;
        const int r = tid >> 3;    // 0..15
#pragma unroll
        for (int p = 0; p < 2; p++) {
            const __half* gq =
                (p ? qkvl : qkvh) + (tok0 + (size_t)qt * 128) * C3 + h * DD + u * 8;
            const uint32_t sq = sb + (p ? AQL : AQH);
#pragma unroll
            for (int it = 0; it < 8; it++) {
                int row = r + it * 16;
                cp16(sq + SWZ(row * 128 + u * 16), gq + (size_t)row * C3);
            }
        }
    }

    auto ld_kv = [&](int kc, int st) {
        const int u = tid & 7;
        const int r = tid >> 3;    // 0..15
        const uint32_t sst = sb + AST(st);
        const size_t trow = tok0 + (size_t)kc * 64;
        const __half* gK = qkvh + trow * C3 + CC + h * DD + u * 8;
        const __half* gV = qkvh + trow * C3 + 2 * CC + h * DD + u * 8;
#pragma unroll
        for (int it = 0; it < 4; it++) {
            int row = r + it * 16;
            uint32_t so = SWZ(row * 128 + u * 16);
            cp16(sst + so,        gK + (size_t)row * C3);
            cp16(sst + 8192 + so, gV + (size_t)row * C3);
        }
    };

    const int nch = 2 * qt + 2;
    ld_kv(0, 0);
    CP_COMMIT();
    if (nch > 1) { ld_kv(1, 1); CP_COMMIT(); }

    uint32_t qh[2][4][4], ql[2][4][4];
    float o[2][8][4];
#pragma unroll
    for (int mi = 0; mi < 2; mi++)
#pragma unroll
        for (int j = 0; j < 8; j++)
#pragma unroll
            for (int t = 0; t < 4; t++) o[mi][j][t] = 0.f;
    float mm0[2] = {-1e30f, -1e30f}, mm1[2] = {-1e30f, -1e30f};
    float ll0[2] = {0.f, 0.f},       ll1[2] = {0.f, 0.f};

    const int qrow_lo = qt * 128 + wid * 32;          // warp's first q row
    const int r0 = lane >> 2;
    const int c0 = (lane & 3) * 2;

    for (int kc = 0; kc < nch; kc++) {
        if (kc + 1 < nch) CP_WAIT(1); else CP_WAIT(0);
        __syncthreads();

        if (kc == 0) {
            // Q fragments (persistent): 2 mi blocks of 16 rows
#pragma unroll
            for (int mi = 0; mi < 2; mi++) {
#pragma unroll
                for (int ks = 0; ks < 4; ks++) {
                    const int rA = lane & 15;
                    const int uA = ks * 2 + (lane >> 4);
                    uint32_t a = SWZ((wid * 32 + mi * 16 + rA) * 128 + uA * 16);
                    LDSM4(qh[mi][ks], sb + AQH + a);
                    LDSM4(ql[mi][ks], sb + AQL + a);
                }
            }
        }

        if (kc * 64 <= qrow_lo + 31) {
            const uint32_t sK = sb + AST(kc & 1);
            const uint32_t sV = sK + 8192;

            // ---- S = Q @ K^T (2-term) ----
            float s[2][8][4];
#pragma unroll
            for (int mi = 0; mi < 2; mi++)
#pragma unroll
                for (int j = 0; j < 8; j++)
#pragma unroll
                    for (int t = 0; t < 4; t++) s[mi][j][t] = 0.f;

            const int rB = (lane & 7) + ((lane & 16) >> 1);
#pragma unroll
            for (int ks = 0; ks < 4; ks++) {
                const int uB = ks * 2 + ((lane & 8) >> 3);
#pragma unroll
                for (int nb = 0; nb < 4; nb++) {
                    uint32_t kh4[4];
                    LDSM4(kh4, sK + SWZ((nb * 16 + rB) * 128 + uB * 16));
#pragma unroll
                    for (int mi = 0; mi < 2; mi++) {
                        MMA16816(s[mi][nb * 2 + 0], qh[mi][ks], kh4[0], kh4[1]);
                        MMA16816(s[mi][nb * 2 + 1], qh[mi][ks], kh4[2], kh4[3]);
                        MMA16816(s[mi][nb * 2 + 0], ql[mi][ks], kh4[0], kh4[1]);
                        MMA16816(s[mi][nb * 2 + 1], ql[mi][ks], kh4[2], kh4[3]);
                    }
                }
            }

            // ---- causal mask (near diagonal only) ----
            if (kc * 64 + 63 > qrow_lo) {
#pragma unroll
                for (int mi = 0; mi < 2; mi++) {
                    const int qr0 = qrow_lo + mi * 16 + r0;
#pragma unroll
                    for (int j = 0; j < 8; j++) {
                        int kcol = kc * 64 + 8 * j + c0;
                        if (kcol > qr0)         s[mi][j][0] = -1e30f;
                        if (kcol + 1 > qr0)     s[mi][j][1] = -1e30f;
                        if (kcol > qr0 + 8)     s[mi][j][2] = -1e30f;
                        if (kcol + 1 > qr0 + 8) s[mi][j][3] = -1e30f;
                    }
                }
            }

            // ---- online softmax + pack P (fp16 hi/lo), per mi ----
            uint32_t ph[2][4][4], pl[2][4][4];
#pragma unroll
            for (int mi = 0; mi < 2; mi++) {
                float mx0 = -1e30f, mx1 = -1e30f;
#pragma unroll
                for (int j = 0; j < 8; j++) {
                    mx0 = fmaxf(mx0, fmaxf(s[mi][j][0], s[mi][j][1]));
                    mx1 = fmaxf(mx1, fmaxf(s[mi][j][2], s[mi][j][3]));
                }
                mx0 = fmaxf(mx0, __shfl_xor_sync(0xffffffffu, mx0, 1));
                mx0 = fmaxf(mx0, __shfl_xor_sync(0xffffffffu, mx0, 2));
                mx1 = fmaxf(mx1, __shfl_xor_sync(0xffffffffu, mx1, 1));
                mx1 = fmaxf(mx1, __shfl_xor_sync(0xffffffffu, mx1, 2));
                float mn0 = fmaxf(mm0[mi], mx0);
                float mn1 = fmaxf(mm1[mi], mx1);
                float corr0 = __expf(mm0[mi] - mn0);
                float corr1 = __expf(mm1[mi] - mn1);
                float ls0 = 0.f, ls1 = 0.f;
#pragma unroll
                for (int j = 0; j < 8; j++) {
                    s[mi][j][0] = __expf(s[mi][j][0] - mn0);
                    s[mi][j][1] = __expf(s[mi][j][1] - mn0);
                    s[mi][j][2] = __expf(s[mi][j][2] - mn1);
                    s[mi][j][3] = __expf(s[mi][j][3] - mn1);
                    ls0 += s[mi][j][0] + s[mi][j][1];
                    ls1 += s[mi][j][2] + s[mi][j][3];
                }
                ls0 += __shfl_xor_sync(0xffffffffu, ls0, 1);
                ls0 += __shfl_xor_sync(0xffffffffu, ls0, 2);
                ls1 += __shfl_xor_sync(0xffffffffu, ls1, 1);
                ls1 += __shfl_xor_sync(0xffffffffu, ls1, 2);
                ll0[mi] = ll0[mi] * corr0 + ls0;
                ll1[mi] = ll1[mi] * corr1 + ls1;
                mm0[mi] = mn0; mm1[mi] = mn1;
#pragma unroll
                for (int j = 0; j < 8; j++) {
                    o[mi][j][0] *= corr0; o[mi][j][1] *= corr0;
                    o[mi][j][2] *= corr1; o[mi][j][3] *= corr1;
                }
#pragma unroll
                for (int ks = 0; ks < 4; ks++) {
                    const int j0 = 2 * ks, j1 = 2 * ks + 1;
                    float v0 = s[mi][j0][0], v1 = s[mi][j0][1];
                    float v2 = s[mi][j0][2], v3 = s[mi][j0][3];
                    float w0 = s[mi][j1][0], w1 = s[mi][j1][1];
                    float w2 = s[mi][j1][2], w3 = s[mi][j1][3];
                    ph[mi][ks][0] = pack_h2(v0, v1);
                    ph[mi][ks][1] = pack_h2(v2, v3);
                    ph[mi][ks][2] = pack_h2(w0, w1);
                    ph[mi][ks][3] = pack_h2(w2, w3);
                    __half2 hh;
                    hh = *(__half2*)&ph[mi][ks][0];
                    pl[mi][ks][0] = pack_h2(v0 - __half2float(hh.x),
                                            v1 - __half2float(hh.y));
                    hh = *(__half2*)&ph[mi][ks][1];
                    pl[mi][ks][1] = pack_h2(v2 - __half2float(hh.x),
                                            v3 - __half2float(hh.y));
                    hh = *(__half2*)&ph[mi][ks][2];
                    pl[mi][ks][2] = pack_h2(w0 - __half2float(hh.x),
                                            w1 - __half2float(hh.y));
                    hh = *(__half2*)&ph[mi][ks][3];
                    pl[mi][ks][3] = pack_h2(w2 - __half2float(hh.x),
                                            w3 - __half2float(hh.y));
                }
            }

            // ---- O += P @ V (V^T fragments via ldmatrix.trans, 2-term) ----
#pragma unroll
            for (int ks = 0; ks < 4; ks++) {
#pragma unroll
                for (int db = 0; db < 4; db++) {
                    uint32_t vh4[4];
                    uint32_t a = SWZ((ks * 16 + (lane & 7) + ((lane >> 3) & 1) * 8) * 128 +
                                     ((lane >> 4) + db * 2) * 16);
                    LDSM4T(vh4, sV + a);
#pragma unroll
                    for (int mi = 0; mi < 2; mi++) {
                        MMA16816(o[mi][db * 2 + 0], ph[mi][ks], vh4[0], vh4[1]);
                        MMA16816(o[mi][db * 2 + 1], ph[mi][ks], vh4[2], vh4[3]);
                        MMA16816(o[mi][db * 2 + 0], pl[mi][ks], vh4[0], vh4[1]);
                        MMA16816(o[mi][db * 2 + 1], pl[mi][ks], vh4[2], vh4[3]);
                    }
                }
            }
        }

        __syncthreads();
        if (kc + 2 < nch) {
            ld_kv(kc + 2, kc & 1);
            CP_COMMIT();
        }
    }

    // ---- epilogue: normalize, split hi/lo (fp16), write yh/yl ----
#pragma unroll
    for (int mi = 0; mi < 2; mi++) {
        const float i0 = 1.f / ll0[mi];
        const float i1 = 1.f / ll1[mi];
        const size_t tokA = tok0 + (size_t)qt * 128 + wid * 32 + mi * 16 + r0;
#pragma unroll
        for (int j = 0; j < 8; j++) {
            int dc = h * DD + 8 * j + c0;
            float a0 = o[mi][j][0] * i0, a1 = o[mi][j][1] * i0;
            float b0 = o[mi][j][2] * i1, b1 = o[mi][j][3] * i1;
            __half h0 = __float2half_rn(a0), h1 = __float2half_rn(a1);
            __half h2 = __float2half_rn(b0), h3 = __float2half_rn(b1);
            size_t offA = tokA * CC + dc;
            size_t offB = (tokA + 8) * CC + dc;
            *(__half2*)(yh + offA) = __half2(h0, h1);
            *(__half2*)(yh + offB) = __half2(h2, h3);
            *(__half2*)(yl + offA) = __half2(
                __float2half_rn(a0 - __half2float(h0)),
                __float2half_rn(a1 - __half2float(h1)));
            *(__half2*)(yl + offB) = __half2(
                __float2half_rn(b0 - __half2float(h2)),
                __float2half_rn(b1 - __half2float(h3)));
        }
    }
}

// ---------------------------------------------------------------------------
extern "C" void kernel_launch(void* const* d_in, const int* in_sizes, int n_in,
                              void* d_out, int out_size) {
    const float* x      = (const float*)d_in[0];
    const float* w_attn = (const float*)d_in[1];
    const float* w_proj = (const float*)d_in[2];
    float* out = (float*)d_out;

    void *xh_p, *xl_p, *wah_p, *wph_p, *qh_p, *ql_p, *yh_p, *yl_p;
    cudaGetSymbolAddress(&xh_p, g_xh);
    cudaGetSymbolAddress(&xl_p, g_xl);
    cudaGetSymbolAddress(&wah_p, g_wah);
    cudaGetSymbolAddress(&wph_p, g_wph);
    cudaGetSymbolAddress(&qh_p, g_qkvh);
    cudaGetSymbolAddress(&ql_p, g_qkvl);
    cudaGetSymbolAddress(&yh_p, g_yh);
    cudaGetSymbolAddress(&yl_p, g_yl);

    cudaFuncSetAttribute(gemm_hmma2<true>,
                         cudaFuncAttributeMaxDynamicSharedMemorySize, GEMM_SMEM);
    cudaFuncSetAttribute(gemm_hmma2<false>,
                         cudaFuncAttributeMaxDynamicSharedMemorySize, GEMM_SMEM);
    cudaFuncSetAttribute(attn_hmma,
                         cudaFuncAttributeMaxDynamicSharedMemorySize, ATTN_SMEM);

    // 1) x -> fp16 hi/lo; weights -> fp16 hi only
    split_f16<true><<<(MM * CC / 4 + 255) / 256, 256>>>(
        x, (__half*)xh_p, (__half*)xl_p, MM * CC / 4);
    split_f16<false><<<(C3 * CC / 4 + 255) / 256, 256>>>(
        w_attn, (__half*)wah_p, nullptr, C3 * CC / 4);
    split_f16<false><<<(CC * CC / 4 + 255) / 256, 256>>>(
        w_proj, (__half*)wph_p, nullptr, CC * CC / 4);

    // 2) QKV gemm: Q cols 2-term (hi+lo out, scaled 1/8); K/V cols 1-term (hi)
    gemm_hmma2<true><<<dim3(C3 / 128, MM / 128), 128, GEMM_SMEM>>>(
        (const __half*)xh_p, (const __half*)xl_p, (const __half*)wah_p,
        nullptr, (__half*)qh_p, (__half*)ql_p, MM, C3, CC);

    // 3) HMMA flash attention -> yh/yl
    attn_hmma<<<dim3(TT / 128, HH, BB), 128, ATTN_SMEM>>>(
        (const __half*)qh_p, (const __half*)ql_p,
        (__half*)yh_p, (__half*)yl_p);

    // 4) out = y @ w_proj^T (fp32 out, 2-term)
    gemm_hmma2<false><<<dim3(CC / 128, MM / 128), 128, GEMM_SMEM>>>(
        (const __half*)yh_p, (const __half*)yl_p, (const __half*)wph_p,
        out, nullptr, nullptr, MM, CC, CC);
}

// round 12
// speedup vs baseline: 2.1996x; 1.1986x over previous
#include <cuda_runtime.h>
#include <cuda_fp16.h>
#include <cstdint>
#include <math.h>

// Problem dims
#define BB 2
#define TT 2048
#define CC 1024
#define HH 16
#define DD 64
#define C3 3072
#define MM (BB * TT)   // 4096

// ---------------------------------------------------------------------------
// Scratch (device globals; no allocation allowed)
// ---------------------------------------------------------------------------
__device__ __half g_xh[(size_t)MM * CC];
__device__ __half g_xl[(size_t)MM * CC];
__device__ __half g_wah[(size_t)C3 * CC];
__device__ __half g_wph[(size_t)CC * CC];
__device__ __half g_qkvh[(size_t)MM * C3];
__device__ __half g_qkvl[(size_t)MM * C3];   // lo only used/written for q cols
__device__ __half g_yh[(size_t)MM * CC];

// ---------------------------------------------------------------------------
// Helpers (sm_103 base-target: ldmatrix / mma.sync / cp.async)
// ---------------------------------------------------------------------------
__device__ __forceinline__ uint32_t smem_to_u32(const void* p) {
    uint32_t a;
    asm("{ .reg .u64 t; cvta.to.shared.u64 t, %1; cvt.u32.u64 %0, t; }"
        : "=r"(a) : "l"(p));
    return a;
}

#define SWZ(off) ((off) ^ (((off) >> 3) & 0x70))

__device__ __forceinline__ void cp16(uint32_t saddr, const void* g) {
    asm volatile("cp.async.cg.shared.global [%0], [%1], 16;"
                 :: "r"(saddr), "l"(g));
}
#define CP_COMMIT() asm volatile("cp.async.commit_group;" ::: "memory")
#define CP_WAIT(n)  asm volatile("cp.async.wait_group %0;" :: "n"(n) : "memory")

#define LDSM4(r, addr) \
    asm volatile("ldmatrix.sync.aligned.m8n8.x4.shared.b16 {%0,%1,%2,%3}, [%4];" \
        : "=r"((r)[0]), "=r"((r)[1]), "=r"((r)[2]), "=r"((r)[3]) : "r"(addr))

#define LDSM4T(r, addr) \
    asm volatile("ldmatrix.sync.aligned.m8n8.x4.trans.shared.b16 {%0,%1,%2,%3}, [%4];" \
        : "=r"((r)[0]), "=r"((r)[1]), "=r"((r)[2]), "=r"((r)[3]) : "r"(addr))

// fp16 MMA, fp32 accumulate
#define MMA16816(d, a, b0v, b1v) \
    asm volatile("mma.sync.aligned.m16n8k16.row.col.f32.f16.f16.f32 " \
        "{%0,%1,%2,%3}, {%4,%5,%6,%7}, {%8,%9}, {%0,%1,%2,%3};" \
        : "+f"((d)[0]), "+f"((d)[1]), "+f"((d)[2]), "+f"((d)[3]) \
        : "r"((a)[0]), "r"((a)[1]), "r"((a)[2]), "r"((a)[3]), "r"(b0v), "r"(b1v))

__device__ __forceinline__ uint32_t pack_h2(float a, float b) {
    __half2 t = __floats2half2_rn(a, b);
    return *(uint32_t*)&t;
}

// ---------------------------------------------------------------------------
// fp32 -> fp16 hi(+lo) planes
// ---------------------------------------------------------------------------
template <bool LO>
__global__ void __launch_bounds__(256) split_f16(const float* __restrict__ in,
                                                 __half* __restrict__ hi,
                                                 __half* __restrict__ lo,
                                                 int n4) {
    int i = blockIdx.x * 256 + threadIdx.x;
    if (i >= n4) return;
    float4 v = ((const float4*)in)[i];
    __half h0 = __float2half_rn(v.x);
    __half h1 = __float2half_rn(v.y);
    __half h2 = __float2half_rn(v.z);
    __half h3 = __float2half_rn(v.w);
    ((__half2*)hi)[i * 2 + 0] = __half2(h0, h1);
    ((__half2*)hi)[i * 2 + 1] = __half2(h2, h3);
    if (LO) {
        __half l0 = __float2half_rn(v.x - __half2float(h0));
        __half l1 = __float2half_rn(v.y - __half2float(h1));
        __half l2 = __float2half_rn(v.z - __half2float(h2));
        __half l3 = __float2half_rn(v.w - __half2float(h3));
        ((__half2*)lo)[i * 2 + 0] = __half2(l0, l1);
        ((__half2*)lo)[i * 2 + 1] = __half2(l2, l3);
    }
}

// ---------------------------------------------------------------------------
// HMMA GEMM: C[M,N] = A[M,K] @ B[N,K]^T, A = Ah(+Al) fp16, B = Bh fp16.
// Tile 128x128, K-chunk 64, 128 thr (4 warps 2x2), warp tile 64x64.
// 2-stage cp.async @ 96KB smem -> 2 CTAs/SM.
// SPLIT=true (QKV): Q cols (bn<1024) 2-term, write hi+lo, scaled 1/8;
//                   K/V cols 1-term, write hi only.
// SPLIT=false (proj): 1-term (TWOTERM=false), fp32 output.
// ---------------------------------------------------------------------------
#define NSTAGE 2
#define STAGE_BYTES 49152          // AH 16K | AL 16K | BH 16K
#define GEMM_SMEM (NSTAGE * STAGE_BYTES)   // 98304

template <bool SPLIT, bool TWOTERM_ALL>
__global__ void __launch_bounds__(128, 2) gemm_hmma2(
    const __half* __restrict__ Ah, const __half* __restrict__ Al,
    const __half* __restrict__ Bh,
    float* __restrict__ C, __half* __restrict__ Ch, __half* __restrict__ Cl,
    int M, int N, int K) {
    extern __shared__ char smem[];
    const uint32_t sbase = smem_to_u32(smem);
    const int tid = threadIdx.x;
    const int lane = tid & 31;
    const int wid = tid >> 5;      // 0..3
    const int wm = wid >> 1;       // 0..1
    const int wn = wid & 1;        // 0..1
    const int bm = blockIdx.y * 128;
    const int bn = blockIdx.x * 128;

    const bool twoterm = SPLIT ? (bn < 1024) : TWOTERM_ALL;

    float acc[4][8][4];
#pragma unroll
    for (int i = 0; i < 4; i++)
#pragma unroll
        for (int j = 0; j < 8; j++)
#pragma unroll
            for (int t = 0; t < 4; t++) acc[i][j][t] = 0.f;

    const int nch = K >> 6;        // K-chunk 64
    const int uL = tid & 7;        // 16B unit within 128B row
    const int rowL = tid >> 3;     // 0..15

    auto ld_chunk = [&](int c, int st) {
        const int k0 = c << 6;
        const uint32_t sS = sbase + st * STAGE_BYTES;
        const __half* gAh = Ah + (size_t)bm * K + k0 + uL * 8;
        const __half* gAl = Al + (size_t)bm * K + k0 + uL * 8;
        const __half* gB  = Bh + (size_t)bn * K + k0 + uL * 8;
#pragma unroll
        for (int it = 0; it < 8; it++) {
            int row = rowL + it * 16;
            uint32_t so = SWZ(row * 128 + uL * 16);
            cp16(sS + so,         gAh + (size_t)row * K);
            if (twoterm) cp16(sS + 16384 + so, gAl + (size_t)row * K);
            cp16(sS + 32768 + so, gB + (size_t)row * K);
        }
    };

    // 2-term compute: Ah*Bh + Al*Bh
    auto compute2 = [&](int st) {
        const uint32_t sAH = sbase + st * STAGE_BYTES;
        const uint32_t sAL = sAH + 16384;
        const uint32_t sBH = sAH + 32768;
#pragma unroll
        for (int ks = 0; ks < 4; ks++) {
            uint32_t ah[4][4], al[4][4];
            const int rA = lane & 15;
            const int uA = ks * 2 + (lane >> 4);
#pragma unroll
            for (int mi = 0; mi < 4; mi++) {
                int mrow = wm * 64 + mi * 16 + rA;
                uint32_t so = SWZ(mrow * 128 + uA * 16);
                LDSM4(ah[mi], sAH + so);
                LDSM4(al[mi], sAL + so);
            }
            const int rB = (lane & 7) + ((lane & 16) >> 1);
            const int uB = ks * 2 + ((lane & 8) >> 3);
#pragma unroll
            for (int nb = 0; nb < 4; nb++) {
                int nrow = wn * 64 + nb * 16 + rB;
                uint32_t bh[4];
                LDSM4(bh, sBH + SWZ(nrow * 128 + uB * 16));
#pragma unroll
                for (int mi = 0; mi < 4; mi++) {
                    MMA16816(acc[mi][nb * 2 + 0], ah[mi], bh[0], bh[1]);
                    MMA16816(acc[mi][nb * 2 + 1], ah[mi], bh[2], bh[3]);
                    MMA16816(acc[mi][nb * 2 + 0], al[mi], bh[0], bh[1]);
                    MMA16816(acc[mi][nb * 2 + 1], al[mi], bh[2], bh[3]);
                }
            }
        }
    };

    // 1-term compute: Ah*Bh only
    auto compute1 = [&](int st) {
        const uint32_t sAH = sbase + st * STAGE_BYTES;
        const uint32_t sBH = sAH + 32768;
#pragma unroll
        for (int ks = 0; ks < 4; ks++) {
            uint32_t ah[4][4];
            const int rA = lane & 15;
            const int uA = ks * 2 + (lane >> 4);
#pragma unroll
            for (int mi = 0; mi < 4; mi++) {
                int mrow = wm * 64 + mi * 16 + rA;
                LDSM4(ah[mi], sAH + SWZ(mrow * 128 + uA * 16));
            }
            const int rB = (lane & 7) + ((lane & 16) >> 1);
            const int uB = ks * 2 + ((lane & 8) >> 3);
#pragma unroll
            for (int nb = 0; nb < 4; nb++) {
                int nrow = wn * 64 + nb * 16 + rB;
                uint32_t bh[4];
                LDSM4(bh, sBH + SWZ(nrow * 128 + uB * 16));
#pragma unroll
                for (int mi = 0; mi < 4; mi++) {
                    MMA16816(acc[mi][nb * 2 + 0], ah[mi], bh[0], bh[1]);
                    MMA16816(acc[mi][nb * 2 + 1], ah[mi], bh[2], bh[3]);
                }
            }
        }
    };

    ld_chunk(0, 0); CP_COMMIT();
    if (nch > 1) { ld_chunk(1, 1); CP_COMMIT(); }

    for (int c = 0; c < nch; c++) {
        if (c + 1 < nch) CP_WAIT(1);
        else             CP_WAIT(0);
        __syncthreads();
        if (twoterm) compute2(c & 1);
        else         compute1(c & 1);
        __syncthreads();
        if (c + 2 < nch) {
            ld_chunk(c + 2, c & 1);
            CP_COMMIT();
        }
    }

    // Epilogue
    const int er = lane >> 2;
    const int ec = (lane & 3) * 2;
    const bool qreg = (bn < 1024);
    const float sc = (SPLIT && qreg) ? 0.125f : 1.0f;   // fold q scale
#pragma unroll
    for (int mi = 0; mi < 4; mi++) {
#pragma unroll
        for (int nj = 0; nj < 8; nj++) {
            int row = bm + wm * 64 + mi * 16 + er;
            int col = bn + wn * 64 + nj * 8 + ec;
            if (SPLIT) {
#pragma unroll
                for (int rr = 0; rr < 2; rr++) {
                    float a0 = acc[mi][nj][rr * 2 + 0] * sc;
                    float a1 = acc[mi][nj][rr * 2 + 1] * sc;
                    __half h0 = __float2half_rn(a0);
                    __half h1 = __float2half_rn(a1);
                    size_t off = (size_t)(row + rr * 8) * N + col;
                    *(__half2*)(Ch + off) = __half2(h0, h1);
                    if (qreg) {   // lo plane needed only for q
                        __half l0 = __float2half_rn(a0 - __half2float(h0));
                        __half l1 = __float2half_rn(a1 - __half2float(h1));
                        *(__half2*)(Cl + off) = __half2(l0, l1);
                    }
                }
            } else {
                float2 v0 = make_float2(acc[mi][nj][0], acc[mi][nj][1]);
                float2 v1 = make_float2(acc[mi][nj][2], acc[mi][nj][3]);
                *(float2*)(C + (size_t)row * N + col) = v0;
                *(float2*)(C + (size_t)(row + 8) * N + col) = v1;
            }
        }
    }
}

// ---------------------------------------------------------------------------
// HMMA flash attention (causal), fp16. CTA = 128 q rows, 4 warps (32 each).
// Q split hi/lo (2-term QK — logits need it); PV 1-term (P fp16 hi only,
// error ~1.4e-4). K/V hi-plane only. Writes yh only.
// ---------------------------------------------------------------------------
#define AQH 0
#define AQL 16384
#define AST(s) (32768 + (s) * 16384)   // stage: KH +0 (8K), VH +8192 (8K)
#define ATTN_SMEM (32768 + 2 * 16384)  // 65536

__global__ void __launch_bounds__(128) attn_hmma(
    const __half* __restrict__ qkvh, const __half* __restrict__ qkvl,
    __half* __restrict__ yh) {
    extern __shared__ char smem[];
    const uint32_t sb = smem_to_u32(smem);
    const int qt = blockIdx.x;
    const int h  = blockIdx.y;
    const int b  = blockIdx.z;
    const int tid = threadIdx.x;
    const int lane = tid & 31;
    const int wid = tid >> 5;      // 0..3, each warp owns 32 q rows

    const size_t tok0 = (size_t)b * TT;

    // ---- Q tile load (128 rows x 64 d, hi+lo) ----
    {
        const int u = tid & 7;
        const int r = tid >> 3;    // 0..15
#pragma unroll
        for (int p = 0; p < 2; p++) {
            const __half* gq =
                (p ? qkvl : qkvh) + (tok0 + (size_t)qt * 128) * C3 + h * DD + u * 8;
            const uint32_t sq = sb + (p ? AQL : AQH);
#pragma unroll
            for (int it = 0; it < 8; it++) {
                int row = r + it * 16;
                cp16(sq + SWZ(row * 128 + u * 16), gq + (size_t)row * C3);
            }
        }
    }

    auto ld_kv = [&](int kc, int st) {
        const int u = tid & 7;
        const int r = tid >> 3;    // 0..15
        const uint32_t sst = sb + AST(st);
        const size_t trow = tok0 + (size_t)kc * 64;
        const __half* gK = qkvh + trow * C3 + CC + h * DD + u * 8;
        const __half* gV = qkvh + trow * C3 + 2 * CC + h * DD + u * 8;
#pragma unroll
        for (int it = 0; it < 4; it++) {
            int row = r + it * 16;
            uint32_t so = SWZ(row * 128 + u * 16);
            cp16(sst + so,        gK + (size_t)row * C3);
            cp16(sst + 8192 + so, gV + (size_t)row * C3);
        }
    };

    const int nch = 2 * qt + 2;
    ld_kv(0, 0);
    CP_COMMIT();
    if (nch > 1) { ld_kv(1, 1); CP_COMMIT(); }

    uint32_t qh[2][4][4], ql[2][4][4];
    float o[2][8][4];
#pragma unroll
    for (int mi = 0; mi < 2; mi++)
#pragma unroll
        for (int j = 0; j < 8; j++)
#pragma unroll
            for (int t = 0; t < 4; t++) o[mi][j][t] = 0.f;
    float mm0[2] = {-1e30f, -1e30f}, mm1[2] = {-1e30f, -1e30f};
    float ll0[2] = {0.f, 0.f},       ll1[2] = {0.f, 0.f};

    const int qrow_lo = qt * 128 + wid * 32;          // warp's first q row
    const int r0 = lane >> 2;
    const int c0 = (lane & 3) * 2;

    for (int kc = 0; kc < nch; kc++) {
        if (kc + 1 < nch) CP_WAIT(1); else CP_WAIT(0);
        __syncthreads();

        if (kc == 0) {
            // Q fragments (persistent): 2 mi blocks of 16 rows
#pragma unroll
            for (int mi = 0; mi < 2; mi++) {
#pragma unroll
                for (int ks = 0; ks < 4; ks++) {
                    const int rA = lane & 15;
                    const int uA = ks * 2 + (lane >> 4);
                    uint32_t a = SWZ((wid * 32 + mi * 16 + rA) * 128 + uA * 16);
                    LDSM4(qh[mi][ks], sb + AQH + a);
                    LDSM4(ql[mi][ks], sb + AQL + a);
                }
            }
        }

        if (kc * 64 <= qrow_lo + 31) {
            const uint32_t sK = sb + AST(kc & 1);
            const uint32_t sV = sK + 8192;

            // ---- S = Q @ K^T (2-term) ----
            float s[2][8][4];
#pragma unroll
            for (int mi = 0; mi < 2; mi++)
#pragma unroll
                for (int j = 0; j < 8; j++)
#pragma unroll
                    for (int t = 0; t < 4; t++) s[mi][j][t] = 0.f;

            const int rB = (lane & 7) + ((lane & 16) >> 1);
#pragma unroll
            for (int ks = 0; ks < 4; ks++) {
                const int uB = ks * 2 + ((lane & 8) >> 3);
#pragma unroll
                for (int nb = 0; nb < 4; nb++) {
                    uint32_t kh4[4];
                    LDSM4(kh4, sK + SWZ((nb * 16 + rB) * 128 + uB * 16));
#pragma unroll
                    for (int mi = 0; mi < 2; mi++) {
                        MMA16816(s[mi][nb * 2 + 0], qh[mi][ks], kh4[0], kh4[1]);
                        MMA16816(s[mi][nb * 2 + 1], qh[mi][ks], kh4[2], kh4[3]);
                        MMA16816(s[mi][nb * 2 + 0], ql[mi][ks], kh4[0], kh4[1]);
                        MMA16816(s[mi][nb * 2 + 1], ql[mi][ks], kh4[2], kh4[3]);
                    }
                }
            }

            // ---- causal mask (near diagonal only) ----
            if (kc * 64 + 63 > qrow_lo) {
#pragma unroll
                for (int mi = 0; mi < 2; mi++) {
                    const int qr0 = qrow_lo + mi * 16 + r0;
#pragma unroll
                    for (int j = 0; j < 8; j++) {
                        int kcol = kc * 64 + 8 * j + c0;
                        if (kcol > qr0)         s[mi][j][0] = -1e30f;
                        if (kcol + 1 > qr0)     s[mi][j][1] = -1e30f;
                        if (kcol > qr0 + 8)     s[mi][j][2] = -1e30f;
                        if (kcol + 1 > qr0 + 8) s[mi][j][3] = -1e30f;
                    }
                }
            }

            // ---- online softmax + pack P (fp16 hi only), per mi ----
            uint32_t ph[2][4][4];
#pragma unroll
            for (int mi = 0; mi < 2; mi++) {
                float mx0 = -1e30f, mx1 = -1e30f;
#pragma unroll
                for (int j = 0; j < 8; j++) {
                    mx0 = fmaxf(mx0, fmaxf(s[mi][j][0], s[mi][j][1]));
                    mx1 = fmaxf(mx1, fmaxf(s[mi][j][2], s[mi][j][3]));
                }
                mx0 = fmaxf(mx0, __shfl_xor_sync(0xffffffffu, mx0, 1));
                mx0 = fmaxf(mx0, __shfl_xor_sync(0xffffffffu, mx0, 2));
                mx1 = fmaxf(mx1, __shfl_xor_sync(0xffffffffu, mx1, 1));
                mx1 = fmaxf(mx1, __shfl_xor_sync(0xffffffffu, mx1, 2));
                float mn0 = fmaxf(mm0[mi], mx0);
                float mn1 = fmaxf(mm1[mi], mx1);
                float corr0 = __expf(mm0[mi] - mn0);
                float corr1 = __expf(mm1[mi] - mn1);
                float ls0 = 0.f, ls1 = 0.f;
#pragma unroll
                for (int j = 0; j < 8; j++) {
                    s[mi][j][0] = __expf(s[mi][j][0] - mn0);
                    s[mi][j][1] = __expf(s[mi][j][1] - mn0);
                    s[mi][j][2] = __expf(s[mi][j][2] - mn1);
                    s[mi][j][3] = __expf(s[mi][j][3] - mn1);
                    ls0 += s[mi][j][0] + s[mi][j][1];
                    ls1 += s[mi][j][2] + s[mi][j][3];
                }
                ls0 += __shfl_xor_sync(0xffffffffu, ls0, 1);
                ls0 += __shfl_xor_sync(0xffffffffu, ls0, 2);
                ls1 += __shfl_xor_sync(0xffffffffu, ls1, 1);
                ls1 += __shfl_xor_sync(0xffffffffu, ls1, 2);
                ll0[mi] = ll0[mi] * corr0 + ls0;
                ll1[mi] = ll1[mi] * corr1 + ls1;
                mm0[mi] = mn0; mm1[mi] = mn1;
#pragma unroll
                for (int j = 0; j < 8; j++) {
                    o[mi][j][0] *= corr0; o[mi][j][1] *= corr0;
                    o[mi][j][2] *= corr1; o[mi][j][3] *= corr1;
                }
#pragma unroll
                for (int ks = 0; ks < 4; ks++) {
                    const int j0 = 2 * ks, j1 = 2 * ks + 1;
                    ph[mi][ks][0] = pack_h2(s[mi][j0][0], s[mi][j0][1]);
                    ph[mi][ks][1] = pack_h2(s[mi][j0][2], s[mi][j0][3]);
                    ph[mi][ks][2] = pack_h2(s[mi][j1][0], s[mi][j1][1]);
                    ph[mi][ks][3] = pack_h2(s[mi][j1][2], s[mi][j1][3]);
                }
            }

            // ---- O += P @ V (V^T via ldmatrix.trans, 1-term) ----
#pragma unroll
            for (int ks = 0; ks < 4; ks++) {
#pragma unroll
                for (int db = 0; db < 4; db++) {
                    uint32_t vh4[4];
                    uint32_t a = SWZ((ks * 16 + (lane & 7) + ((lane >> 3) & 1) * 8) * 128 +
                                     ((lane >> 4) + db * 2) * 16);
                    LDSM4T(vh4, sV + a);
#pragma unroll
                    for (int mi = 0; mi < 2; mi++) {
                        MMA16816(o[mi][db * 2 + 0], ph[mi][ks], vh4[0], vh4[1]);
                        MMA16816(o[mi][db * 2 + 1], ph[mi][ks], vh4[2], vh4[3]);
                    }
                }
            }
        }

        __syncthreads();
        if (kc + 2 < nch) {
            ld_kv(kc + 2, kc & 1);
            CP_COMMIT();
        }
    }

    // ---- epilogue: normalize, write yh (fp16) ----
#pragma unroll
    for (int mi = 0; mi < 2; mi++) {
        const float i0 = 1.f / ll0[mi];
        const float i1 = 1.f / ll1[mi];
        const size_t tokA = tok0 + (size_t)qt * 128 + wid * 32 + mi * 16 + r0;
#pragma unroll
        for (int j = 0; j < 8; j++) {
            int dc = h * DD + 8 * j + c0;
            float a0 = o[mi][j][0] * i0, a1 = o[mi][j][1] * i0;
            float b0 = o[mi][j][2] * i1, b1 = o[mi][j][3] * i1;
            *(__half2*)(yh + tokA * CC + dc) =
                __half2(__float2half_rn(a0), __float2half_rn(a1));
            *(__half2*)(yh + (tokA + 8) * CC + dc) =
                __half2(__float2half_rn(b0), __float2half_rn(b1));
        }
    }
}

// ---------------------------------------------------------------------------
extern "C" void kernel_launch(void* const* d_in, const int* in_sizes, int n_in,
                              void* d_out, int out_size) {
    const float* x      = (const float*)d_in[0];
    const float* w_attn = (const float*)d_in[1];
    const float* w_proj = (const float*)d_in[2];
    float* out = (float*)d_out;

    void *xh_p, *xl_p, *wah_p, *wph_p, *qh_p, *ql_p, *yh_p;
    cudaGetSymbolAddress(&xh_p, g_xh);
    cudaGetSymbolAddress(&xl_p, g_xl);
    cudaGetSymbolAddress(&wah_p, g_wah);
    cudaGetSymbolAddress(&wph_p, g_wph);
    cudaGetSymbolAddress(&qh_p, g_qkvh);
    cudaGetSymbolAddress(&ql_p, g_qkvl);
    cudaGetSymbolAddress(&yh_p, g_yh);

    cudaFuncSetAttribute((const void*)gemm_hmma2<true, true>,
                         cudaFuncAttributeMaxDynamicSharedMemorySize, GEMM_SMEM);
    cudaFuncSetAttribute((const void*)gemm_hmma2<false, false>,
                         cudaFuncAttributeMaxDynamicSharedMemorySize, GEMM_SMEM);
    cudaFuncSetAttribute(attn_hmma,
                         cudaFuncAttributeMaxDynamicSharedMemorySize, ATTN_SMEM);

    // 1) x -> fp16 hi/lo; weights -> fp16 hi only
    split_f16<true><<<(MM * CC / 4 + 255) / 256, 256>>>(
        x, (__half*)xh_p, (__half*)xl_p, MM * CC / 4);
    split_f16<false><<<(C3 * CC / 4 + 255) / 256, 256>>>(
        w_attn, (__half*)wah_p, nullptr, C3 * CC / 4);
    split_f16<false><<<(CC * CC / 4 + 255) / 256, 256>>>(
        w_proj, (__half*)wph_p, nullptr, CC * CC / 4);

    // 2) QKV gemm: Q cols 2-term (hi+lo out, scaled 1/8); K/V cols 1-term (hi)
    gemm_hmma2<true, true><<<dim3(C3 / 128, MM / 128), 128, GEMM_SMEM>>>(
        (const __half*)xh_p, (const __half*)xl_p, (const __half*)wah_p,
        nullptr, (__half*)qh_p, (__half*)ql_p, MM, C3, CC);

    // 3) HMMA flash attention -> yh (fp16 hi only)
    attn_hmma<<<dim3(TT / 128, HH, BB), 128, ATTN_SMEM>>>(
        (const __half*)qh_p, (const __half*)ql_p, (__half*)yh_p);

    // 4) out = yh @ w_proj^T (1-term, fp32 out)
    gemm_hmma2<false, false><<<dim3(CC / 128, MM / 128), 128, GEMM_SMEM>>>(
        (const __half*)yh_p, nullptr, (const __half*)wph_p,
        out, nullptr, nullptr, MM, CC, CC);
}

// round 13
// speedup vs baseline: 2.2965x; 1.0441x over previous
#include <cuda_runtime.h>
#include <cuda_fp16.h>
#include <cstdint>
#include <math.h>

// Problem dims
#define BB 2
#define TT 2048
#define CC 1024
#define HH 16
#define DD 64
#define C3 3072
#define MM (BB * TT)   // 4096

// ---------------------------------------------------------------------------
// Scratch (device globals; no allocation allowed)
// ---------------------------------------------------------------------------
__device__ __half g_xh[(size_t)MM * CC];
__device__ __half g_xl[(size_t)MM * CC];
__device__ __half g_wah[(size_t)C3 * CC];
__device__ __half g_wph[(size_t)CC * CC];
__device__ __half g_qkvh[(size_t)MM * C3];
__device__ __half g_qkvl[(size_t)MM * C3];   // lo only used/written for q cols
__device__ __half g_yh[(size_t)MM * CC];

// ---------------------------------------------------------------------------
// Helpers (sm_103 base-target: ldmatrix / mma.sync / cp.async)
// ---------------------------------------------------------------------------
__device__ __forceinline__ uint32_t smem_to_u32(const void* p) {
    uint32_t a;
    asm("{ .reg .u64 t; cvta.to.shared.u64 t, %1; cvt.u32.u64 %0, t; }"
        : "=r"(a) : "l"(p));
    return a;
}

#define SWZ(off) ((off) ^ (((off) >> 3) & 0x70))

__device__ __forceinline__ void cp16(uint32_t saddr, const void* g) {
    asm volatile("cp.async.cg.shared.global [%0], [%1], 16;"
                 :: "r"(saddr), "l"(g));
}
#define CP_COMMIT() asm volatile("cp.async.commit_group;" ::: "memory")
#define CP_WAIT(n)  asm volatile("cp.async.wait_group %0;" :: "n"(n) : "memory")

#define LDSM4(r, addr) \
    asm volatile("ldmatrix.sync.aligned.m8n8.x4.shared.b16 {%0,%1,%2,%3}, [%4];" \
        : "=r"((r)[0]), "=r"((r)[1]), "=r"((r)[2]), "=r"((r)[3]) : "r"(addr))

#define LDSM4T(r, addr) \
    asm volatile("ldmatrix.sync.aligned.m8n8.x4.trans.shared.b16 {%0,%1,%2,%3}, [%4];" \
        : "=r"((r)[0]), "=r"((r)[1]), "=r"((r)[2]), "=r"((r)[3]) : "r"(addr))

// fp16 MMA, fp32 accumulate
#define MMA16816(d, a, b0v, b1v) \
    asm volatile("mma.sync.aligned.m16n8k16.row.col.f32.f16.f16.f32 " \
        "{%0,%1,%2,%3}, {%4,%5,%6,%7}, {%8,%9}, {%0,%1,%2,%3};" \
        : "+f"((d)[0]), "+f"((d)[1]), "+f"((d)[2]), "+f"((d)[3]) \
        : "r"((a)[0]), "r"((a)[1]), "r"((a)[2]), "r"((a)[3]), "r"(b0v), "r"(b1v))

__device__ __forceinline__ uint32_t pack_h2(float a, float b) {
    __half2 t = __floats2half2_rn(a, b);
    return *(uint32_t*)&t;
}

// ---------------------------------------------------------------------------
// Fused split: one launch converts x (hi+lo), w_attn (hi), w_proj (hi).
// ---------------------------------------------------------------------------
#define N4_X  (MM * CC / 4)          // 1048576
#define N4_WA (C3 * CC / 4)          // 786432
#define N4_WP (CC * CC / 4)          // 262144
#define N4_TOTAL (N4_X + N4_WA + N4_WP)

__global__ void __launch_bounds__(256) fused_split(
    const float* __restrict__ x, const float* __restrict__ wa,
    const float* __restrict__ wp,
    __half* __restrict__ xh, __half* __restrict__ xl,
    __half* __restrict__ wah, __half* __restrict__ wph) {
    int i = blockIdx.x * 256 + threadIdx.x;
    if (i >= N4_TOTAL) return;

    const float* src;
    __half* hi;
    bool lo_needed = false;
    int j;
    if (i < N4_X) {
        src = x; hi = xh; j = i; lo_needed = true;
    } else if (i < N4_X + N4_WA) {
        src = wa; hi = wah; j = i - N4_X;
    } else {
        src = wp; hi = wph; j = i - N4_X - N4_WA;
    }

    float4 v = ((const float4*)src)[j];
    __half h0 = __float2half_rn(v.x);
    __half h1 = __float2half_rn(v.y);
    __half h2 = __float2half_rn(v.z);
    __half h3 = __float2half_rn(v.w);
    ((__half2*)hi)[j * 2 + 0] = __half2(h0, h1);
    ((__half2*)hi)[j * 2 + 1] = __half2(h2, h3);
    if (lo_needed) {
        __half l0 = __float2half_rn(v.x - __half2float(h0));
        __half l1 = __float2half_rn(v.y - __half2float(h1));
        __half l2 = __float2half_rn(v.z - __half2float(h2));
        __half l3 = __float2half_rn(v.w - __half2float(h3));
        ((__half2*)xl)[j * 2 + 0] = __half2(l0, l1);
        ((__half2*)xl)[j * 2 + 1] = __half2(l2, l3);
    }
}

// ---------------------------------------------------------------------------
// HMMA GEMM: C[M,N] = A[M,K] @ B[N,K]^T, A = Ah(+Al) fp16, B = Bh fp16.
// Tile 128x128, K-chunk 64, 128 thr (4 warps 2x2), warp tile 64x64.
// 2-stage cp.async @ 96KB smem -> 2 CTAs/SM.
// SPLIT=true (QKV): Q cols (bn<1024) 2-term, write hi+lo,
//   scaled by 0.125*log2(e) (softmax runs in exp2 domain);
//   K/V cols 1-term, write hi only.
// SPLIT=false (proj): 1-term, fp32 output.
// ---------------------------------------------------------------------------
#define NSTAGE 2
#define STAGE_BYTES 49152          // AH 16K | AL 16K | BH 16K
#define GEMM_SMEM (NSTAGE * STAGE_BYTES)   // 98304
#define QSCALE (0.125f * 1.4426950408889634f)   // 1/sqrt(64) * log2(e)

template <bool SPLIT, bool TWOTERM_ALL>
__global__ void __launch_bounds__(128, 2) gemm_hmma2(
    const __half* __restrict__ Ah, const __half* __restrict__ Al,
    const __half* __restrict__ Bh,
    float* __restrict__ C, __half* __restrict__ Ch, __half* __restrict__ Cl,
    int M, int N, int K) {
    extern __shared__ char smem[];
    const uint32_t sbase = smem_to_u32(smem);
    const int tid = threadIdx.x;
    const int lane = tid & 31;
    const int wid = tid >> 5;      // 0..3
    const int wm = wid >> 1;       // 0..1
    const int wn = wid & 1;        // 0..1
    const int bm = blockIdx.y * 128;
    const int bn = blockIdx.x * 128;

    const bool twoterm = SPLIT ? (bn < 1024) : TWOTERM_ALL;

    float acc[4][8][4];
#pragma unroll
    for (int i = 0; i < 4; i++)
#pragma unroll
        for (int j = 0; j < 8; j++)
#pragma unroll
            for (int t = 0; t < 4; t++) acc[i][j][t] = 0.f;

    const int nch = K >> 6;        // K-chunk 64
    const int uL = tid & 7;        // 16B unit within 128B row
    const int rowL = tid >> 3;     // 0..15

    auto ld_chunk = [&](int c, int st) {
        const int k0 = c << 6;
        const uint32_t sS = sbase + st * STAGE_BYTES;
        const __half* gAh = Ah + (size_t)bm * K + k0 + uL * 8;
        const __half* gAl = Al + (size_t)bm * K + k0 + uL * 8;
        const __half* gB  = Bh + (size_t)bn * K + k0 + uL * 8;
#pragma unroll
        for (int it = 0; it < 8; it++) {
            int row = rowL + it * 16;
            uint32_t so = SWZ(row * 128 + uL * 16);
            cp16(sS + so,         gAh + (size_t)row * K);
            if (twoterm) cp16(sS + 16384 + so, gAl + (size_t)row * K);
            cp16(sS + 32768 + so, gB + (size_t)row * K);
        }
    };

    // 2-term compute: Ah*Bh + Al*Bh
    auto compute2 = [&](int st) {
        const uint32_t sAH = sbase + st * STAGE_BYTES;
        const uint32_t sAL = sAH + 16384;
        const uint32_t sBH = sAH + 32768;
#pragma unroll
        for (int ks = 0; ks < 4; ks++) {
            uint32_t ah[4][4], al[4][4];
            const int rA = lane & 15;
            const int uA = ks * 2 + (lane >> 4);
#pragma unroll
            for (int mi = 0; mi < 4; mi++) {
                int mrow = wm * 64 + mi * 16 + rA;
                uint32_t so = SWZ(mrow * 128 + uA * 16);
                LDSM4(ah[mi], sAH + so);
                LDSM4(al[mi], sAL + so);
            }
            const int rB = (lane & 7) + ((lane & 16) >> 1);
            const int uB = ks * 2 + ((lane & 8) >> 3);
#pragma unroll
            for (int nb = 0; nb < 4; nb++) {
                int nrow = wn * 64 + nb * 16 + rB;
                uint32_t bh[4];
                LDSM4(bh, sBH + SWZ(nrow * 128 + uB * 16));
#pragma unroll
                for (int mi = 0; mi < 4; mi++) {
                    MMA16816(acc[mi][nb * 2 + 0], ah[mi], bh[0], bh[1]);
                    MMA16816(acc[mi][nb * 2 + 1], ah[mi], bh[2], bh[3]);
                    MMA16816(acc[mi][nb * 2 + 0], al[mi], bh[0], bh[1]);
                    MMA16816(acc[mi][nb * 2 + 1], al[mi], bh[2], bh[3]);
                }
            }
        }
    };

    // 1-term compute: Ah*Bh only
    auto compute1 = [&](int st) {
        const uint32_t sAH = sbase + st * STAGE_BYTES;
        const uint32_t sBH = sAH + 32768;
#pragma unroll
        for (int ks = 0; ks < 4; ks++) {
            uint32_t ah[4][4];
            const int rA = lane & 15;
            const int uA = ks * 2 + (lane >> 4);
#pragma unroll
            for (int mi = 0; mi < 4; mi++) {
                int mrow = wm * 64 + mi * 16 + rA;
                LDSM4(ah[mi], sAH + SWZ(mrow * 128 + uA * 16));
            }
            const int rB = (lane & 7) + ((lane & 16) >> 1);
            const int uB = ks * 2 + ((lane & 8) >> 3);
#pragma unroll
            for (int nb = 0; nb < 4; nb++) {
                int nrow = wn * 64 + nb * 16 + rB;
                uint32_t bh[4];
                LDSM4(bh, sBH + SWZ(nrow * 128 + uB * 16));
#pragma unroll
                for (int mi = 0; mi < 4; mi++) {
                    MMA16816(acc[mi][nb * 2 + 0], ah[mi], bh[0], bh[1]);
                    MMA16816(acc[mi][nb * 2 + 1], ah[mi], bh[2], bh[3]);
                }
            }
        }
    };

    ld_chunk(0, 0); CP_COMMIT();
    if (nch > 1) { ld_chunk(1, 1); CP_COMMIT(); }

    for (int c = 0; c < nch; c++) {
        if (c + 1 < nch) CP_WAIT(1);
        else             CP_WAIT(0);
        __syncthreads();
        if (twoterm) compute2(c & 1);
        else         compute1(c & 1);
        __syncthreads();
        if (c + 2 < nch) {
            ld_chunk(c + 2, c & 1);
            CP_COMMIT();
        }
    }

    // Epilogue
    const int er = lane >> 2;
    const int ec = (lane & 3) * 2;
    const bool qreg = (bn < 1024);
    const float sc = (SPLIT && qreg) ? QSCALE : 1.0f;   // fold q scale + log2e
#pragma unroll
    for (int mi = 0; mi < 4; mi++) {
#pragma unroll
        for (int nj = 0; nj < 8; nj++) {
            int row = bm + wm * 64 + mi * 16 + er;
            int col = bn + wn * 64 + nj * 8 + ec;
            if (SPLIT) {
#pragma unroll
                for (int rr = 0; rr < 2; rr++) {
                    float a0 = acc[mi][nj][rr * 2 + 0] * sc;
                    float a1 = acc[mi][nj][rr * 2 + 1] * sc;
                    __half h0 = __float2half_rn(a0);
                    __half h1 = __float2half_rn(a1);
                    size_t off = (size_t)(row + rr * 8) * N + col;
                    *(__half2*)(Ch + off) = __half2(h0, h1);
                    if (qreg) {   // lo plane needed only for q
                        __half l0 = __float2half_rn(a0 - __half2float(h0));
                        __half l1 = __float2half_rn(a1 - __half2float(h1));
                        *(__half2*)(Cl + off) = __half2(l0, l1);
                    }
                }
            } else {
                float2 v0 = make_float2(acc[mi][nj][0], acc[mi][nj][1]);
                float2 v1 = make_float2(acc[mi][nj][2], acc[mi][nj][3]);
                *(float2*)(C + (size_t)row * N + col) = v0;
                *(float2*)(C + (size_t)(row + 8) * N + col) = v1;
            }
        }
    }
}

// ---------------------------------------------------------------------------
// HMMA flash attention (causal), fp16. CTA = 128 q rows, 4 warps (32 each).
// Q split hi/lo (2-term QK); PV 1-term. K/V hi-plane only. Writes yh only.
// Logits arrive pre-scaled by log2(e) -> softmax uses exp2f.
// LPT: qt reversed so heaviest CTAs launch first.
// ---------------------------------------------------------------------------
#define AQH 0
#define AQL 16384
#define AST(s) (32768 + (s) * 16384)   // stage: KH +0 (8K), VH +8192 (8K)
#define ATTN_SMEM (32768 + 2 * 16384)  // 65536

__global__ void __launch_bounds__(128) attn_hmma(
    const __half* __restrict__ qkvh, const __half* __restrict__ qkvl,
    __half* __restrict__ yh) {
    extern __shared__ char smem[];
    const uint32_t sb = smem_to_u32(smem);
    const int qt = (gridDim.x - 1) - blockIdx.x;   // LPT: heavy tiles first
    const int h  = blockIdx.y;
    const int b  = blockIdx.z;
    const int tid = threadIdx.x;
    const int lane = tid & 31;
    const int wid = tid >> 5;      // 0..3, each warp owns 32 q rows

    const size_t tok0 = (size_t)b * TT;

    // ---- Q tile load (128 rows x 64 d, hi+lo) ----
    {
        const int u = tid & 7;
        const int r = tid >> 3;    // 0..15
#pragma unroll
        for (int p = 0; p < 2; p++) {
            const __half* gq =
                (p ? qkvl : qkvh) + (tok0 + (size_t)qt * 128) * C3 + h * DD + u * 8;
            const uint32_t sq = sb + (p ? AQL : AQH);
#pragma unroll
            for (int it = 0; it < 8; it++) {
                int row = r + it * 16;
                cp16(sq + SWZ(row * 128 + u * 16), gq + (size_t)row * C3);
            }
        }
    }

    auto ld_kv = [&](int kc, int st) {
        const int u = tid & 7;
        const int r = tid >> 3;    // 0..15
        const uint32_t sst = sb + AST(st);
        const size_t trow = tok0 + (size_t)kc * 64;
        const __half* gK = qkvh + trow * C3 + CC + h * DD + u * 8;
        const __half* gV = qkvh + trow * C3 + 2 * CC + h * DD + u * 8;
#pragma unroll
        for (int it = 0; it < 4; it++) {
            int row = r + it * 16;
            uint32_t so = SWZ(row * 128 + u * 16);
            cp16(sst + so,        gK + (size_t)row * C3);
            cp16(sst + 8192 + so, gV + (size_t)row * C3);
        }
    };

    const int nch = 2 * qt + 2;
    ld_kv(0, 0);
    CP_COMMIT();
    if (nch > 1) { ld_kv(1, 1); CP_COMMIT(); }

    uint32_t qh[2][4][4], ql[2][4][4];
    float o[2][8][4];
#pragma unroll
    for (int mi = 0; mi < 2; mi++)
#pragma unroll
        for (int j = 0; j < 8; j++)
#pragma unroll
            for (int t = 0; t < 4; t++) o[mi][j][t] = 0.f;
    float mm0[2] = {-1e30f, -1e30f}, mm1[2] = {-1e30f, -1e30f};
    float ll0[2] = {0.f, 0.f},       ll1[2] = {0.f, 0.f};

    const int qrow_lo = qt * 128 + wid * 32;          // warp's first q row
    const int r0 = lane >> 2;
    const int c0 = (lane & 3) * 2;

    for (int kc = 0; kc < nch; kc++) {
        if (kc + 1 < nch) CP_WAIT(1); else CP_WAIT(0);
        __syncthreads();

        if (kc == 0) {
            // Q fragments (persistent): 2 mi blocks of 16 rows
#pragma unroll
            for (int mi = 0; mi < 2; mi++) {
#pragma unroll
                for (int ks = 0; ks < 4; ks++) {
                    const int rA = lane & 15;
                    const int uA = ks * 2 + (lane >> 4);
                    uint32_t a = SWZ((wid * 32 + mi * 16 + rA) * 128 + uA * 16);
                    LDSM4(qh[mi][ks], sb + AQH + a);
                    LDSM4(ql[mi][ks], sb + AQL + a);
                }
            }
        }

        if (kc * 64 <= qrow_lo + 31) {
            const uint32_t sK = sb + AST(kc & 1);
            const uint32_t sV = sK + 8192;

            // ---- S = Q @ K^T (2-term, log2 domain) ----
            float s[2][8][4];
#pragma unroll
            for (int mi = 0; mi < 2; mi++)
#pragma unroll
                for (int j = 0; j < 8; j++)
#pragma unroll
                    for (int t = 0; t < 4; t++) s[mi][j][t] = 0.f;

            const int rB = (lane & 7) + ((lane & 16) >> 1);
#pragma unroll
            for (int ks = 0; ks < 4; ks++) {
                const int uB = ks * 2 + ((lane & 8) >> 3);
#pragma unroll
                for (int nb = 0; nb < 4; nb++) {
                    uint32_t kh4[4];
                    LDSM4(kh4, sK + SWZ((nb * 16 + rB) * 128 + uB * 16));
#pragma unroll
                    for (int mi = 0; mi < 2; mi++) {
                        MMA16816(s[mi][nb * 2 + 0], qh[mi][ks], kh4[0], kh4[1]);
                        MMA16816(s[mi][nb * 2 + 1], qh[mi][ks], kh4[2], kh4[3]);
                        MMA16816(s[mi][nb * 2 + 0], ql[mi][ks], kh4[0], kh4[1]);
                        MMA16816(s[mi][nb * 2 + 1], ql[mi][ks], kh4[2], kh4[3]);
                    }
                }
            }

            // ---- causal mask (near diagonal only) ----
            if (kc * 64 + 63 > qrow_lo) {
#pragma unroll
                for (int mi = 0; mi < 2; mi++) {
                    const int qr0 = qrow_lo + mi * 16 + r0;
#pragma unroll
                    for (int j = 0; j < 8; j++) {
                        int kcol = kc * 64 + 8 * j + c0;
                        if (kcol > qr0)         s[mi][j][0] = -1e30f;
                        if (kcol + 1 > qr0)     s[mi][j][1] = -1e30f;
                        if (kcol > qr0 + 8)     s[mi][j][2] = -1e30f;
                        if (kcol + 1 > qr0 + 8) s[mi][j][3] = -1e30f;
                    }
                }
            }

            // ---- online softmax (exp2 domain) + pack P (fp16 hi), per mi ----
            uint32_t ph[2][4][4];
#pragma unroll
            for (int mi = 0; mi < 2; mi++) {
                float mx0 = -1e30f, mx1 = -1e30f;
#pragma unroll
                for (int j = 0; j < 8; j++) {
                    mx0 = fmaxf(mx0, fmaxf(s[mi][j][0], s[mi][j][1]));
                    mx1 = fmaxf(mx1, fmaxf(s[mi][j][2], s[mi][j][3]));
                }
                mx0 = fmaxf(mx0, __shfl_xor_sync(0xffffffffu, mx0, 1));
                mx0 = fmaxf(mx0, __shfl_xor_sync(0xffffffffu, mx0, 2));
                mx1 = fmaxf(mx1, __shfl_xor_sync(0xffffffffu, mx1, 1));
                mx1 = fmaxf(mx1, __shfl_xor_sync(0xffffffffu, mx1, 2));
                float mn0 = fmaxf(mm0[mi], mx0);
                float mn1 = fmaxf(mm1[mi], mx1);
                float corr0 = exp2f(mm0[mi] - mn0);
                float corr1 = exp2f(mm1[mi] - mn1);
                float ls0 = 0.f, ls1 = 0.f;
#pragma unroll
                for (int j = 0; j < 8; j++) {
                    s[mi][j][0] = exp2f(s[mi][j][0] - mn0);
                    s[mi][j][1] = exp2f(s[mi][j][1] - mn0);
                    s[mi][j][2] = exp2f(s[mi][j][2] - mn1);
                    s[mi][j][3] = exp2f(s[mi][j][3] - mn1);
                    ls0 += s[mi][j][0] + s[mi][j][1];
                    ls1 += s[mi][j][2] + s[mi][j][3];
                }
                ls0 += __shfl_xor_sync(0xffffffffu, ls0, 1);
                ls0 += __shfl_xor_sync(0xffffffffu, ls0, 2);
                ls1 += __shfl_xor_sync(0xffffffffu, ls1, 1);
                ls1 += __shfl_xor_sync(0xffffffffu, ls1, 2);
                ll0[mi] = ll0[mi] * corr0 + ls0;
                ll1[mi] = ll1[mi] * corr1 + ls1;
                mm0[mi] = mn0; mm1[mi] = mn1;
#pragma unroll
                for (int j = 0; j < 8; j++) {
                    o[mi][j][0] *= corr0; o[mi][j][1] *= corr0;
                    o[mi][j][2] *= corr1; o[mi][j][3] *= corr1;
                }
#pragma unroll
                for (int ks = 0; ks < 4; ks++) {
                    const int j0 = 2 * ks, j1 = 2 * ks + 1;
                    ph[mi][ks][0] = pack_h2(s[mi][j0][0], s[mi][j0][1]);
                    ph[mi][ks][1] = pack_h2(s[mi][j0][2], s[mi][j0][3]);
                    ph[mi][ks][2] = pack_h2(s[mi][j1][0], s[mi][j1][1]);
                    ph[mi][ks][3] = pack_h2(s[mi][j1][2], s[mi][j1][3]);
                }
            }

            // ---- O += P @ V (V^T via ldmatrix.trans, 1-term) ----
#pragma unroll
            for (int ks = 0; ks < 4; ks++) {
#pragma unroll
                for (int db = 0; db < 4; db++) {
                    uint32_t vh4[4];
                    uint32_t a = SWZ((ks * 16 + (lane & 7) + ((lane >> 3) & 1) * 8) * 128 +
                                     ((lane >> 4) + db * 2) * 16);
                    LDSM4T(vh4, sV + a);
#pragma unroll
                    for (int mi = 0; mi < 2; mi++) {
                        MMA16816(o[mi][db * 2 + 0], ph[mi][ks], vh4[0], vh4[1]);
                        MMA16816(o[mi][db * 2 + 1], ph[mi][ks], vh4[2], vh4[3]);
                    }
                }
            }
        }

        __syncthreads();
        if (kc + 2 < nch) {
            ld_kv(kc + 2, kc & 1);
            CP_COMMIT();
        }
    }

    // ---- epilogue: normalize, write yh (fp16) ----
#pragma unroll
    for (int mi = 0; mi < 2; mi++) {
        const float i0 = 1.f / ll0[mi];
        const float i1 = 1.f / ll1[mi];
        const size_t tokA = tok0 + (size_t)qt * 128 + wid * 32 + mi * 16 + r0;
#pragma unroll
        for (int j = 0; j < 8; j++) {
            int dc = h * DD + 8 * j + c0;
            float a0 = o[mi][j][0] * i0, a1 = o[mi][j][1] * i0;
            float b0 = o[mi][j][2] * i1, b1 = o[mi][j][3] * i1;
            *(__half2*)(yh + tokA * CC + dc) =
                __half2(__float2half_rn(a0), __float2half_rn(a1));
            *(__half2*)(yh + (tokA + 8) * CC + dc) =
                __half2(__float2half_rn(b0), __float2half_rn(b1));
        }
    }
}

// ---------------------------------------------------------------------------
extern "C" void kernel_launch(void* const* d_in, const int* in_sizes, int n_in,
                              void* d_out, int out_size) {
    const float* x      = (const float*)d_in[0];
    const float* w_attn = (const float*)d_in[1];
    const float* w_proj = (const float*)d_in[2];
    float* out = (float*)d_out;

    void *xh_p, *xl_p, *wah_p, *wph_p, *qh_p, *ql_p, *yh_p;
    cudaGetSymbolAddress(&xh_p, g_xh);
    cudaGetSymbolAddress(&xl_p, g_xl);
    cudaGetSymbolAddress(&wah_p, g_wah);
    cudaGetSymbolAddress(&wph_p, g_wph);
    cudaGetSymbolAddress(&qh_p, g_qkvh);
    cudaGetSymbolAddress(&ql_p, g_qkvl);
    cudaGetSymbolAddress(&yh_p, g_yh);

    cudaFuncSetAttribute((const void*)gemm_hmma2<true, true>,
                         cudaFuncAttributeMaxDynamicSharedMemorySize, GEMM_SMEM);
    cudaFuncSetAttribute((const void*)gemm_hmma2<false, false>,
                         cudaFuncAttributeMaxDynamicSharedMemorySize, GEMM_SMEM);
    cudaFuncSetAttribute(attn_hmma,
                         cudaFuncAttributeMaxDynamicSharedMemorySize, ATTN_SMEM);

    // 1) One fused split: x -> hi/lo; w_attn, w_proj -> hi
    fused_split<<<(N4_TOTAL + 255) / 256, 256>>>(
        x, w_attn, w_proj,
        (__half*)xh_p, (__half*)xl_p, (__half*)wah_p, (__half*)wph_p);

    // 2) QKV gemm: Q cols 2-term (hi+lo out, scaled 0.125*log2e); K/V 1-term
    gemm_hmma2<true, true><<<dim3(C3 / 128, MM / 128), 128, GEMM_SMEM>>>(
        (const __half*)xh_p, (const __half*)xl_p, (const __half*)wah_p,
        nullptr, (__half*)qh_p, (__half*)ql_p, MM, C3, CC);

    // 3) HMMA flash attention -> yh (fp16 hi only), LPT-ordered
    attn_hmma<<<dim3(TT / 128, HH, BB), 128, ATTN_SMEM>>>(
        (const __half*)qh_p, (const __half*)ql_p, (__half*)yh_p);

    // 4) out = yh @ w_proj^T (1-term, fp32 out)
    gemm_hmma2<false, false><<<dim3(CC / 128, MM / 128), 128, GEMM_SMEM>>>(
        (const __half*)yh_p, nullptr, (const __half*)wph_p,
        out, nullptr, nullptr, MM, CC, CC);
}